// round 13
// baseline (speedup 1.0000x reference)
#include <cuda_runtime.h>
#include <cuda_bf16.h>
#include <cmath>

#define BATCH 16
#define NPTS  1024
#define KNN   20
#define EPSBN 1e-5f
#define SLOPE 0.2f

// ---------------- scratch (device globals; no allocations allowed) ----------------
__device__ float g_xT[BATCH * NPTS * 8];
__device__ float g_hcat[BATCH * NPTS * 512];
__device__ float g_pd[(long long)BATCH * NPTS * NPTS];
__device__ int   g_idx[BATCH * NPTS * KNN];
__device__ float g_YZ[BATCH * NPTS * 512];
__device__ float g_W[512 * 128];
__device__ float g_sq[BATCH * NPTS];
__device__ float g_pmax[8 * BATCH * 1024];
__device__ float g_psum[8 * BATCH * 1024];
__device__ float g_pool[BATCH * 2048];
__device__ float g_fc1[BATCH * 512];
__device__ float g_fc2[BATCH * 256];
// split-bf16 buffers
__device__ unsigned short g_Ahi[BATCH * NPTS * 512];
__device__ unsigned short g_Alo[BATCH * NPTS * 512];
__device__ unsigned short g_Bhi[1024 * 512];
__device__ unsigned short g_Blo[1024 * 512];
__device__ unsigned short g_Xhi[BATCH * NPTS * 32];
__device__ unsigned short g_Xlo[BATCH * NPTS * 32];

// ---------------- helpers ----------------
__device__ __forceinline__ unsigned long long pack2(float lo, float hi)
{
    unsigned long long r;
    asm("mov.b64 %0, {%1, %2};" : "=l"(r) : "f"(lo), "f"(hi));
    return r;
}
__device__ __forceinline__ void ffma2(unsigned long long& acc,
                                      unsigned long long a, unsigned long long b)
{
    asm("fma.rn.f32x2 %0, %1, %2, %0;" : "+l"(acc) : "l"(a), "l"(b));
}
__device__ __forceinline__ float2 unpack2(unsigned long long v)
{
    float lo, hi;
    asm("mov.b64 {%0, %1}, %2;" : "=f"(lo), "=f"(hi) : "l"(v));
    return make_float2(lo, hi);
}
__device__ __forceinline__ void mma_bf16(float* d, const unsigned* a, const unsigned* b)
{
    asm volatile(
        "mma.sync.aligned.m16n8k16.row.col.f32.bf16.bf16.f32 "
        "{%0,%1,%2,%3}, {%4,%5,%6,%7}, {%8,%9}, {%0,%1,%2,%3};"
        : "+f"(d[0]), "+f"(d[1]), "+f"(d[2]), "+f"(d[3])
        : "r"(a[0]), "r"(a[1]), "r"(a[2]), "r"(a[3]), "r"(b[0]), "r"(b[1]));
}
__device__ __forceinline__ unsigned short bf_bits(__nv_bfloat16 h)
{
    unsigned short s;
    memcpy(&s, &h, 2);
    return s;
}
__device__ __forceinline__ unsigned pk16(unsigned short a, unsigned short b)
{
    return (unsigned)a | ((unsigned)b << 16);
}

// ---------------- transpose x + split bf16 + sq, all fused ----------------
__global__ void transpose_x_split_kernel(const float* __restrict__ x,
                                         float* __restrict__ xT,
                                         unsigned short* __restrict__ Xhi,
                                         unsigned short* __restrict__ Xlo,
                                         float* __restrict__ sq)
{
    int p = blockIdx.x * blockDim.x + threadIdx.x;
    if (p >= BATCH * NPTS) return;
    int b = p / NPTS;
    int n = p % NPTS;
    const float* xb = x + (long long)b * 3 * NPTS + n;
    float v0 = xb[0], v1 = xb[NPTS], v2 = xb[2 * NPTS];
    *(float4*)&xT[p * 8]     = make_float4(v0, v1, v2, 0.f);
    *(float4*)&xT[p * 8 + 4] = make_float4(0.f, 0.f, 0.f, 0.f);
    sq[p] = v0 * v0 + v1 * v1 + v2 * v2;

    __nv_bfloat16 h0 = __float2bfloat16_rn(v0);
    __nv_bfloat16 h1 = __float2bfloat16_rn(v1);
    __nv_bfloat16 h2 = __float2bfloat16_rn(v2);
    __nv_bfloat16 l0 = __float2bfloat16_rn(v0 - __bfloat162float(h0));
    __nv_bfloat16 l1 = __float2bfloat16_rn(v1 - __bfloat162float(h1));
    __nv_bfloat16 l2 = __float2bfloat16_rn(v2 - __bfloat162float(h2));

    uint4 z = make_uint4(0, 0, 0, 0);
    uint4 vh = make_uint4(pk16(bf_bits(h0), bf_bits(h1)), pk16(bf_bits(h2), 0), 0, 0);
    uint4 vl = make_uint4(pk16(bf_bits(l0), bf_bits(l1)), pk16(bf_bits(l2), 0), 0, 0);
    uint4* ph = (uint4*)(Xhi + p * 32);
    uint4* pl = (uint4*)(Xlo + p * 32);
    ph[0] = vh; ph[1] = z; ph[2] = z; ph[3] = z;
    pl[0] = vl; pl[1] = z; pl[2] = z; pl[3] = z;
}

// ---------------- fp32 -> (hi, lo) bf16 split (w5) ----------------
__global__ void cvt_split4_kernel(const float* __restrict__ in,
                                  unsigned short* __restrict__ hi,
                                  unsigned short* __restrict__ lo, int n4)
{
    int i = blockIdx.x * blockDim.x + threadIdx.x;
    if (i >= n4) return;
    float4 v = ((const float4*)in)[i];
    __nv_bfloat16 h0 = __float2bfloat16_rn(v.x);
    __nv_bfloat16 h1 = __float2bfloat16_rn(v.y);
    __nv_bfloat16 h2 = __float2bfloat16_rn(v.z);
    __nv_bfloat16 h3 = __float2bfloat16_rn(v.w);
    __nv_bfloat16 l0 = __float2bfloat16_rn(v.x - __bfloat162float(h0));
    __nv_bfloat16 l1 = __float2bfloat16_rn(v.y - __bfloat162float(h1));
    __nv_bfloat16 l2 = __float2bfloat16_rn(v.z - __bfloat162float(h2));
    __nv_bfloat16 l3 = __float2bfloat16_rn(v.w - __bfloat162float(h3));
    uint2* hp = (uint2*)(hi + i * 4);
    uint2* lp = (uint2*)(lo + i * 4);
    *hp = make_uint2(pk16(bf_bits(h0), bf_bits(h1)), pk16(bf_bits(h2), bf_bits(h3)));
    *lp = make_uint2(pk16(bf_bits(l0), bf_bits(l1)), pk16(bf_bits(l2), bf_bits(l3)));
}

// ---------------- split-bf16 MMA Gram: pd = 2*H@H^T - sq_m - sq_n --------------
__global__ void __launch_bounds__(256)
gram_mma_kernel(const unsigned short* __restrict__ Hhi,
                const unsigned short* __restrict__ Hlo,
                int ld, int K,
                const float* __restrict__ sq, float* __restrict__ pd)
{
    __shared__ __align__(16) unsigned sah[128 * 20], sal[128 * 20],
                                      sbh[128 * 20], sbl[128 * 20];

    int b = blockIdx.z;
    long long hbase = (long long)b * NPTS * ld;
    const float* sqb = sq + b * NPTS;
    float* pdb = pd + (long long)b * NPTS * NPTS;

    int tid = threadIdx.x;
    int lane = tid & 31;
    int w = tid >> 5;
    int wm = w & 1, wn = w >> 1;
    int gr = lane >> 2, tig = lane & 3;
    int bx = blockIdx.x, by = blockIdx.y;

    int l_row = tid >> 1;
    int q0 = (tid & 1) * 2;
    long long a_base = hbase + (long long)(by * 128 + l_row) * ld;
    long long b_base = hbase + (long long)(bx * 128 + l_row) * ld;

    int nk = K >> 5;

    uint4 pa_h[2], pa_l[2], pb_h[2], pb_l[2];
    #pragma unroll
    for (int q = 0; q < 2; ++q) {
        pa_h[q] = *(const uint4*)(Hhi + a_base + (q0 + q) * 8);
        pa_l[q] = *(const uint4*)(Hlo + a_base + (q0 + q) * 8);
        pb_h[q] = *(const uint4*)(Hhi + b_base + (q0 + q) * 8);
        pb_l[q] = *(const uint4*)(Hlo + b_base + (q0 + q) * 8);
    }

    float acc[4][4][4];
    #pragma unroll
    for (int mt = 0; mt < 4; ++mt)
        #pragma unroll
        for (int nt = 0; nt < 4; ++nt)
            #pragma unroll
            for (int c = 0; c < 4; ++c)
                acc[mt][nt][c] = 0.f;

    for (int kt = 0; kt < nk; ++kt) {
        #pragma unroll
        for (int q = 0; q < 2; ++q) {
            *(uint4*)&sah[l_row * 20 + (q0 + q) * 4] = pa_h[q];
            *(uint4*)&sal[l_row * 20 + (q0 + q) * 4] = pa_l[q];
            *(uint4*)&sbh[l_row * 20 + (q0 + q) * 4] = pb_h[q];
            *(uint4*)&sbl[l_row * 20 + (q0 + q) * 4] = pb_l[q];
        }
        __syncthreads();

        if (kt + 1 < nk) {
            long long koff = (long long)(kt + 1) * 32;
            #pragma unroll
            for (int q = 0; q < 2; ++q) {
                pa_h[q] = *(const uint4*)(Hhi + a_base + koff + (q0 + q) * 8);
                pa_l[q] = *(const uint4*)(Hlo + a_base + koff + (q0 + q) * 8);
                pb_h[q] = *(const uint4*)(Hhi + b_base + koff + (q0 + q) * 8);
                pb_l[q] = *(const uint4*)(Hlo + b_base + koff + (q0 + q) * 8);
            }
        }

        #pragma unroll
        for (int s = 0; s < 2; ++s) {
            unsigned ahf[4][4], alf[4][4];
            #pragma unroll
            for (int mt = 0; mt < 4; ++mt) {
                int r0 = wm * 64 + mt * 16 + gr;
                int p = s * 8 + tig;
                ahf[mt][0] = sah[r0 * 20 + p];
                ahf[mt][1] = sah[(r0 + 8) * 20 + p];
                ahf[mt][2] = sah[r0 * 20 + p + 4];
                ahf[mt][3] = sah[(r0 + 8) * 20 + p + 4];
                alf[mt][0] = sal[r0 * 20 + p];
                alf[mt][1] = sal[(r0 + 8) * 20 + p];
                alf[mt][2] = sal[r0 * 20 + p + 4];
                alf[mt][3] = sal[(r0 + 8) * 20 + p + 4];
            }
            unsigned bhf[4][2], blf[4][2];
            #pragma unroll
            for (int nt = 0; nt < 4; ++nt) {
                int n0 = wn * 32 + nt * 8 + gr;
                int p = s * 8 + tig;
                bhf[nt][0] = sbh[n0 * 20 + p];
                bhf[nt][1] = sbh[n0 * 20 + p + 4];
                blf[nt][0] = sbl[n0 * 20 + p];
                blf[nt][1] = sbl[n0 * 20 + p + 4];
            }
            #pragma unroll
            for (int mt = 0; mt < 4; ++mt)
                #pragma unroll
                for (int nt = 0; nt < 4; ++nt) {
                    mma_bf16(acc[mt][nt], ahf[mt], bhf[nt]);
                    mma_bf16(acc[mt][nt], ahf[mt], blf[nt]);
                    mma_bf16(acc[mt][nt], alf[mt], bhf[nt]);
                }
        }
        __syncthreads();
    }

    #pragma unroll
    for (int mt = 0; mt < 4; ++mt) {
        int r0 = by * 128 + wm * 64 + mt * 16 + gr;
        float sq0 = sqb[r0];
        float sq1 = sqb[r0 + 8];
        #pragma unroll
        for (int nt = 0; nt < 4; ++nt) {
            int c = bx * 128 + wn * 32 + nt * 8 + 2 * tig;
            float sc0 = sqb[c], sc1 = sqb[c + 1];
            *(float2*)&pdb[(long long)r0 * NPTS + c] =
                make_float2(2.f * acc[mt][nt][0] - sq0 - sc0,
                            2.f * acc[mt][nt][1] - sq0 - sc1);
            *(float2*)&pdb[(long long)(r0 + 8) * NPTS + c] =
                make_float2(2.f * acc[mt][nt][2] - sq1 - sc0,
                            2.f * acc[mt][nt][3] - sq1 - sc1);
        }
    }
}

// ---------------- 128x128 tiled SGEMM, f32x2 core (YZ GEMM) ----------------
__global__ void __launch_bounds__(256)
sgemm_nt_kernel(const float* __restrict__ A, const float* __restrict__ Bw,
                float* __restrict__ C,
                int M, int Nn, int K, int lda, int ldb, int ldc)
{
    __shared__ float As[8][128];
    __shared__ float Bs[8][128];

    int tid = threadIdx.x;
    int tx = tid & 15;
    int ty = tid >> 4;
    int bx = blockIdx.x, by = blockIdx.y;

    int l_row = tid >> 1;
    int l_k0  = (tid & 1) * 4;

    const float* aptr = A + (long long)(by * 128 + l_row) * lda + l_k0;
    const float* bptr = Bw + (long long)(bx * 128 + l_row) * ldb + l_k0;

    float4 ra = *(const float4*)aptr;
    float4 rb = *(const float4*)bptr;

    unsigned long long acc2[8][4];
    #pragma unroll
    for (int i = 0; i < 8; ++i)
        #pragma unroll
        for (int j = 0; j < 4; ++j)
            acc2[i][j] = 0ull;

    for (int kt = 0; kt < K; kt += 8) {
        As[l_k0 + 0][l_row] = ra.x;
        As[l_k0 + 1][l_row] = ra.y;
        As[l_k0 + 2][l_row] = ra.z;
        As[l_k0 + 3][l_row] = ra.w;
        Bs[l_k0 + 0][l_row] = rb.x;
        Bs[l_k0 + 1][l_row] = rb.y;
        Bs[l_k0 + 2][l_row] = rb.z;
        Bs[l_k0 + 3][l_row] = rb.w;
        __syncthreads();

        if (kt + 8 < K) {
            ra = *(const float4*)(aptr + kt + 8);
            rb = *(const float4*)(bptr + kt + 8);
        }

        #pragma unroll
        for (int kk = 0; kk < 8; ++kk) {
            float4 a0 = *(const float4*)&As[kk][ty * 8];
            float4 a1 = *(const float4*)&As[kk][ty * 8 + 4];
            float4 b0 = *(const float4*)&Bs[kk][tx * 8];
            float4 b1 = *(const float4*)&Bs[kk][tx * 8 + 4];

            unsigned long long bp[4];
            bp[0] = pack2(b0.x, b0.y);
            bp[1] = pack2(b0.z, b0.w);
            bp[2] = pack2(b1.x, b1.y);
            bp[3] = pack2(b1.z, b1.w);

            float a[8] = {a0.x, a0.y, a0.z, a0.w, a1.x, a1.y, a1.z, a1.w};
            #pragma unroll
            for (int i = 0; i < 8; ++i) {
                unsigned long long ap = pack2(a[i], a[i]);
                #pragma unroll
                for (int j = 0; j < 4; ++j)
                    ffma2(acc2[i][j], ap, bp[j]);
            }
        }
        __syncthreads();
    }

    #pragma unroll
    for (int i = 0; i < 8; ++i) {
        int gm = by * 128 + ty * 8 + i;
        #pragma unroll
        for (int jj = 0; jj < 2; ++jj) {
            float4 v4;
            float2 p0 = unpack2(acc2[i][jj * 2]);
            float2 p1 = unpack2(acc2[i][jj * 2 + 1]);
            v4.x = p0.x; v4.y = p0.y; v4.z = p1.x; v4.w = p1.y;
            *(float4*)&C[(long long)gm * ldc + bx * 128 + tx * 8 + jj * 4] = v4;
        }
    }
}

// ---------------- conv5 split-bf16 MMA + fused BN/LReLU + pooling ---------------
__global__ void __launch_bounds__(256)
conv5_mma_kernel(const unsigned short* __restrict__ Ahi, const unsigned short* __restrict__ Alo,
                 const unsigned short* __restrict__ Bhi, const unsigned short* __restrict__ Blo,
                 const float* __restrict__ bn,
                 float* __restrict__ pmax, float* __restrict__ psum)
{
    __shared__ __align__(16) union SM {
        struct { unsigned ah[128 * 20], al[128 * 20], bh[128 * 20], bl[128 * 20]; } t;
        struct { float rmax[2][128]; float rsum[2][128]; } r;
    } sm;

    int tid = threadIdx.x;
    int lane = tid & 31;
    int w = tid >> 5;
    int wm = w & 1, wn = w >> 1;
    int gr = lane >> 2, tig = lane & 3;
    int bx = blockIdx.x, by = blockIdx.y;

    int l_row = tid >> 1;
    int q0 = (tid & 1) * 2;
    long long a_base = (long long)(by * 128 + l_row) * 512;
    long long b_base = (long long)(bx * 128 + l_row) * 512;

    uint4 pa_h[2], pa_l[2], pb_h[2], pb_l[2];
    #pragma unroll
    for (int q = 0; q < 2; ++q) {
        pa_h[q] = *(const uint4*)(Ahi + a_base + (q0 + q) * 8);
        pa_l[q] = *(const uint4*)(Alo + a_base + (q0 + q) * 8);
        pb_h[q] = *(const uint4*)(Bhi + b_base + (q0 + q) * 8);
        pb_l[q] = *(const uint4*)(Blo + b_base + (q0 + q) * 8);
    }

    float acc[4][4][4];
    #pragma unroll
    for (int mt = 0; mt < 4; ++mt)
        #pragma unroll
        for (int nt = 0; nt < 4; ++nt)
            #pragma unroll
            for (int c = 0; c < 4; ++c)
                acc[mt][nt][c] = 0.f;

    for (int kt = 0; kt < 16; ++kt) {
        #pragma unroll
        for (int q = 0; q < 2; ++q) {
            *(uint4*)&sm.t.ah[l_row * 20 + (q0 + q) * 4] = pa_h[q];
            *(uint4*)&sm.t.al[l_row * 20 + (q0 + q) * 4] = pa_l[q];
            *(uint4*)&sm.t.bh[l_row * 20 + (q0 + q) * 4] = pb_h[q];
            *(uint4*)&sm.t.bl[l_row * 20 + (q0 + q) * 4] = pb_l[q];
        }
        __syncthreads();

        if (kt + 1 < 16) {
            long long koff = (long long)(kt + 1) * 32;
            #pragma unroll
            for (int q = 0; q < 2; ++q) {
                pa_h[q] = *(const uint4*)(Ahi + a_base + koff + (q0 + q) * 8);
                pa_l[q] = *(const uint4*)(Alo + a_base + koff + (q0 + q) * 8);
                pb_h[q] = *(const uint4*)(Bhi + b_base + koff + (q0 + q) * 8);
                pb_l[q] = *(const uint4*)(Blo + b_base + koff + (q0 + q) * 8);
            }
        }

        #pragma unroll
        for (int s = 0; s < 2; ++s) {
            unsigned ahf[4][4], alf[4][4];
            #pragma unroll
            for (int mt = 0; mt < 4; ++mt) {
                int r0 = wm * 64 + mt * 16 + gr;
                int p = s * 8 + tig;
                ahf[mt][0] = sm.t.ah[r0 * 20 + p];
                ahf[mt][1] = sm.t.ah[(r0 + 8) * 20 + p];
                ahf[mt][2] = sm.t.ah[r0 * 20 + p + 4];
                ahf[mt][3] = sm.t.ah[(r0 + 8) * 20 + p + 4];
                alf[mt][0] = sm.t.al[r0 * 20 + p];
                alf[mt][1] = sm.t.al[(r0 + 8) * 20 + p];
                alf[mt][2] = sm.t.al[r0 * 20 + p + 4];
                alf[mt][3] = sm.t.al[(r0 + 8) * 20 + p + 4];
            }
            unsigned bhf[4][2], blf[4][2];
            #pragma unroll
            for (int nt = 0; nt < 4; ++nt) {
                int n0 = wn * 32 + nt * 8 + gr;
                int p = s * 8 + tig;
                bhf[nt][0] = sm.t.bh[n0 * 20 + p];
                bhf[nt][1] = sm.t.bh[n0 * 20 + p + 4];
                blf[nt][0] = sm.t.bl[n0 * 20 + p];
                blf[nt][1] = sm.t.bl[n0 * 20 + p + 4];
            }
            #pragma unroll
            for (int mt = 0; mt < 4; ++mt)
                #pragma unroll
                for (int nt = 0; nt < 4; ++nt) {
                    mma_bf16(acc[mt][nt], ahf[mt], bhf[nt]);
                    mma_bf16(acc[mt][nt], ahf[mt], blf[nt]);
                    mma_bf16(acc[mt][nt], alf[mt], bhf[nt]);
                }
        }
        __syncthreads();
    }

    #pragma unroll
    for (int nt = 0; nt < 4; ++nt) {
        #pragma unroll
        for (int j = 0; j < 2; ++j) {
            int lcol = wn * 32 + nt * 8 + 2 * tig + j;
            int col = bx * 128 + lcol;
            float g  = bn[col];
            float be = bn[1024 + col];
            float mu = bn[2048 + col];
            float va = bn[3072 + col];
            float s = g * rsqrtf(va + EPSBN);
            float o = be - mu * s;
            float mx = -INFINITY, smv = 0.f;
            #pragma unroll
            for (int mt = 0; mt < 4; ++mt) {
                float v0 = s * acc[mt][nt][j] + o;
                v0 = v0 > 0.f ? v0 : SLOPE * v0;
                float v1 = s * acc[mt][nt][2 + j] + o;
                v1 = v1 > 0.f ? v1 : SLOPE * v1;
                mx = fmaxf(mx, fmaxf(v0, v1));
                smv += v0 + v1;
            }
            #pragma unroll
            for (int off = 4; off <= 16; off <<= 1) {
                mx = fmaxf(mx, __shfl_xor_sync(0xffffffffu, mx, off));
                smv += __shfl_xor_sync(0xffffffffu, smv, off);
            }
            if (gr == 0) {
                sm.r.rmax[wm][lcol] = mx;
                sm.r.rsum[wm][lcol] = smv;
            }
        }
    }
    __syncthreads();

    if (tid < 128) {
        int c = tid;
        float mx = fmaxf(sm.r.rmax[0][c], sm.r.rmax[1][c]);
        float s2 = sm.r.rsum[0][c] + sm.r.rsum[1][c];
        int b = by >> 3, chunk = by & 7;
        pmax[((long long)chunk * BATCH + b) * 1024 + bx * 128 + c] = mx;
        psum[((long long)chunk * BATCH + b) * 1024 + bx * 128 + c] = s2;
    }
}

// ---------------- final pool reduce over 8 chunks ----------------
__global__ void pool_reduce_kernel(const float* __restrict__ pmax,
                                   const float* __restrict__ psum,
                                   float* __restrict__ pool)
{
    int gi = blockIdx.x * blockDim.x + threadIdx.x;
    if (gi >= BATCH * 1024) return;
    int b = gi >> 10;
    int c = gi & 1023;
    float mx = -INFINITY, sm = 0.f;
    #pragma unroll
    for (int chunk = 0; chunk < 8; ++chunk) {
        mx = fmaxf(mx, pmax[((long long)chunk * BATCH + b) * 1024 + c]);
        sm += psum[((long long)chunk * BATCH + b) * 1024 + c];
    }
    pool[b * 2048 + c] = mx;
    pool[b * 2048 + 1024 + c] = sm * (1.f / (float)NPTS);
}

// ---------------- warp-per-row top-k (k=20), register-only, no dynamic index ----
// Combined 37-bit key: (monotone_key << 5) | (31 - j). Popped values strictly
// decrease; rescan filters v < lastv with a fully static loop.
__global__ void __launch_bounds__(256) topk_warp_kernel(const float* __restrict__ pd,
                                                        int* __restrict__ out)
{
    int warp_in_blk = threadIdx.x >> 5;
    int lane = threadIdx.x & 31;
    int row = blockIdx.x * 8 + warp_in_blk;

    const float* __restrict__ p = pd + (long long)row * NPTS;

    unsigned k[32];
    #pragma unroll
    for (int j = 0; j < 32; ++j) {
        unsigned u = __float_as_uint(p[j * 32 + lane]);
        k[j] = (u & 0x80000000u) ? ~u : (u | 0x80000000u);
    }

    // sorted top-4 of combined keys (static indexing only)
    unsigned long long c0 = 0, c1 = 0, c2 = 0, c3 = 0;
    #pragma unroll
    for (int j = 0; j < 32; ++j) {
        unsigned long long v = ((unsigned long long)k[j] << 5) | (unsigned)(31 - j);
        if (v > c3) {
            if (v > c2) {
                if (v > c1) {
                    if (v > c0) { c3 = c2; c2 = c1; c1 = c0; c0 = v; }
                    else        { c3 = c2; c2 = c1; c1 = v; }
                } else          { c3 = c2; c2 = v; }
            } else              { c3 = v; }
        }
    }
    unsigned long long lastv = ~0ull;

    int* __restrict__ o = out + (long long)row * KNN;

    #pragma unroll 1
    for (int it = 0; it < KNN; ++it) {
        unsigned hk = (unsigned)(c0 >> 5);
        unsigned m = __reduce_max_sync(0xffffffffu, hk);
        unsigned bal = __ballot_sync(0xffffffffu, hk == m);
        int src = __ffs((int)bal) - 1;
        int jloc = 31 - (int)(c0 & 31u);
        int gi = __shfl_sync(0xffffffffu, (jloc << 5) | lane, src);
        if (lane == 0) o[it] = gi;

        if (lane == src) {
            lastv = c0;
            c0 = c1; c1 = c2; c2 = c3; c3 = 0;
            if (c0 == 0ull) {   // cache drained (rare): static rescan below lastv
                unsigned long long n0 = 0, n1 = 0, n2 = 0, n3 = 0;
                #pragma unroll
                for (int j = 0; j < 32; ++j) {
                    unsigned long long v =
                        ((unsigned long long)k[j] << 5) | (unsigned)(31 - j);
                    if (v < lastv && v > n3) {
                        if (v > n2) {
                            if (v > n1) {
                                if (v > n0) { n3 = n2; n2 = n1; n1 = n0; n0 = v; }
                                else        { n3 = n2; n2 = n1; n1 = v; }
                            } else          { n3 = n2; n2 = v; }
                        } else              { n3 = v; }
                    }
                }
                c0 = n0; c1 = n1; c2 = n2; c3 = n3;
            }
        }
    }
}

// ---------------- prepare edge weights: [wa ; wb - wa], K-padded ----------------
__global__ void prep_w_kernel(const float* __restrict__ w, float* __restrict__ Wc,
                              int O, int C, int Cpad)
{
    int i = blockIdx.x * blockDim.x + threadIdx.x;
    int tot = 2 * O * Cpad;
    if (i >= tot) return;
    int half = i / (O * Cpad);
    int j = i % (O * Cpad);
    int o = j / Cpad, c = j % Cpad;
    float v = 0.f;
    if (c < C)
        v = half == 0 ? w[o * 2 * C + c]
                      : w[o * 2 * C + C + c] - w[o * 2 * C + c];
    Wc[half * O * Cpad + o * Cpad + c] = v;
}

// ---------------- FUSED gather + max_k + BN + LReLU + bf16 split + sq -----------
__global__ void gather_fused_kernel(const float* __restrict__ YZ,
                                    const int* __restrict__ idx,
                                    const float* __restrict__ bn,
                                    float* __restrict__ hcat,
                                    unsigned short* __restrict__ Ahi,
                                    unsigned short* __restrict__ Alo,
                                    float* __restrict__ sq,
                                    int O, int catoff, int writeSq)
{
    int b = blockIdx.y;
    int n0 = blockIdx.x * 8;
    int o4 = threadIdx.x;
    int py = threadIdx.y;
    int n = n0 + py;

    __shared__ int sidx[8][KNN];
    __shared__ float ssq[8][64];
    int bw = blockDim.x * 8;
    for (int t = threadIdx.y * blockDim.x + threadIdx.x; t < 8 * KNN; t += bw)
        sidx[t / KNN][t % KNN] = idx[((long long)b * NPTS + n0 + t / KNN) * KNN + t % KNN];
    __syncthreads();

    int ld = 2 * O;
    const float* base = YZ + (long long)b * NPTS * ld;

    float4 zc = *(const float4*)&base[(long long)n * ld + O + o4 * 4];
    float4 mx = make_float4(-INFINITY, -INFINITY, -INFINITY, -INFINITY);
    float4 mn = make_float4(INFINITY, INFINITY, INFINITY, INFINITY);
    #pragma unroll
    for (int kk = 0; kk < KNN; ++kk) {
        float4 y = *(const float4*)&base[(long long)sidx[py][kk] * ld + o4 * 4];
        mx.x = fmaxf(mx.x, y.x); mn.x = fminf(mn.x, y.x);
        mx.y = fmaxf(mx.y, y.y); mn.y = fminf(mn.y, y.y);
        mx.z = fmaxf(mx.z, y.z); mn.z = fminf(mn.z, y.z);
        mx.w = fmaxf(mx.w, y.w); mn.w = fminf(mn.w, y.w);
    }

    float4 g4  = *(const float4*)&bn[o4 * 4];
    float4 be4 = *(const float4*)&bn[O + o4 * 4];
    float4 mu4 = *(const float4*)&bn[2 * O + o4 * 4];
    float4 va4 = *(const float4*)&bn[3 * O + o4 * 4];

    float4 r;
    {
        float s = g4.x * rsqrtf(va4.x + EPSBN);
        float z = (s >= 0.f ? mx.x : mn.x) + zc.x;
        float v = s * z + (be4.x - mu4.x * s);
        r.x = v > 0.f ? v : SLOPE * v;
    }
    {
        float s = g4.y * rsqrtf(va4.y + EPSBN);
        float z = (s >= 0.f ? mx.y : mn.y) + zc.y;
        float v = s * z + (be4.y - mu4.y * s);
        r.y = v > 0.f ? v : SLOPE * v;
    }
    {
        float s = g4.z * rsqrtf(va4.z + EPSBN);
        float z = (s >= 0.f ? mx.z : mn.z) + zc.z;
        float v = s * z + (be4.z - mu4.z * s);
        r.z = v > 0.f ? v : SLOPE * v;
    }
    {
        float s = g4.w * rsqrtf(va4.w + EPSBN);
        float z = (s >= 0.f ? mx.w : mn.w) + zc.w;
        float v = s * z + (be4.w - mu4.w * s);
        r.w = v > 0.f ? v : SLOPE * v;
    }

    long long off = ((long long)b * NPTS + n) * 512 + catoff + o4 * 4;
    *(float4*)&hcat[off] = r;

    __nv_bfloat16 h0 = __float2bfloat16_rn(r.x);
    __nv_bfloat16 h1 = __float2bfloat16_rn(r.y);
    __nv_bfloat16 h2 = __float2bfloat16_rn(r.z);
    __nv_bfloat16 h3 = __float2bfloat16_rn(r.w);
    __nv_bfloat16 l0 = __float2bfloat16_rn(r.x - __bfloat162float(h0));
    __nv_bfloat16 l1 = __float2bfloat16_rn(r.y - __bfloat162float(h1));
    __nv_bfloat16 l2 = __float2bfloat16_rn(r.z - __bfloat162float(h2));
    __nv_bfloat16 l3 = __float2bfloat16_rn(r.w - __bfloat162float(h3));
    *(uint2*)(Ahi + off) = make_uint2(pk16(bf_bits(h0), bf_bits(h1)),
                                      pk16(bf_bits(h2), bf_bits(h3)));
    *(uint2*)(Alo + off) = make_uint2(pk16(bf_bits(l0), bf_bits(l1)),
                                      pk16(bf_bits(l2), bf_bits(l3)));

    if (writeSq) {
        ssq[py][o4] = r.x * r.x + r.y * r.y + r.z * r.z + r.w * r.w;
        __syncthreads();
        if (o4 == 0) {
            float s = 0.f;
            for (int j = 0; j < blockDim.x; ++j) s += ssq[py][j];
            sq[(long long)b * NPTS + n] = s;
        }
    }
}

// ---------------- FC layer: warp per (b,o) ----------------
__global__ void fc_kernel(const float* __restrict__ in, const float* __restrict__ W,
                          const float* __restrict__ bn, const float* __restrict__ bias,
                          float* __restrict__ out, int O, int K, int Bn)
{
    int gw = (blockIdx.x * blockDim.x + threadIdx.x) >> 5;
    int lane = threadIdx.x & 31;
    if (gw >= Bn * O) return;
    int b = gw / O, o = gw % O;
    float acc = 0.f;
    const float* ip = in + (long long)b * K;
    const float* wp = W + (long long)o * K;
    for (int k = lane; k < K; k += 32) acc += ip[k] * wp[k];
    #pragma unroll
    for (int off = 16; off > 0; off >>= 1)
        acc += __shfl_down_sync(0xffffffffu, acc, off);
    if (lane == 0) {
        float v = acc;
        if (bn) {
            float g  = bn[o];
            float be = bn[O + o];
            float mu = bn[2 * O + o];
            float va = bn[3 * O + o];
            float s = g * rsqrtf(va + EPSBN);
            v = s * v + (be - mu * s);
            v = v > 0.f ? v : SLOPE * v;
        } else {
            v += bias[o];
        }
        out[(long long)b * O + o] = v;
    }
}

// ---------------- host orchestration (R11 structure: default + 1 side stream) ----
extern "C" void kernel_launch(void* const* d_in, const int* in_sizes, int n_in,
                              void* d_out, int out_size)
{
    (void)in_sizes; (void)n_in; (void)out_size;
    const float* x   = (const float*)d_in[0];
    const float* w1  = (const float*)d_in[1];
    const float* bn1 = (const float*)d_in[2];
    const float* w2  = (const float*)d_in[3];
    const float* bn2 = (const float*)d_in[4];
    const float* w3  = (const float*)d_in[5];
    const float* bn3 = (const float*)d_in[6];
    const float* w4  = (const float*)d_in[7];
    const float* bn4 = (const float*)d_in[8];
    const float* w5  = (const float*)d_in[9];
    const float* bn5 = (const float*)d_in[10];
    const float* wl1 = (const float*)d_in[11];
    const float* bn6 = (const float*)d_in[12];
    const float* wl2 = (const float*)d_in[13];
    const float* bn7 = (const float*)d_in[14];
    const float* wl3 = (const float*)d_in[15];
    const float* bl3 = (const float*)d_in[16];
    float* out = (float*)d_out;

    float *p_xT, *p_hcat, *p_pd, *p_YZ, *p_W, *p_sq, *p_pmax, *p_psum,
          *p_pool, *p_fc1, *p_fc2;
    int* p_idx;
    unsigned short *p_Ahi, *p_Alo, *p_Bhi, *p_Blo, *p_Xhi, *p_Xlo;
    cudaGetSymbolAddress((void**)&p_xT,   g_xT);
    cudaGetSymbolAddress((void**)&p_hcat, g_hcat);
    cudaGetSymbolAddress((void**)&p_pd,   g_pd);
    cudaGetSymbolAddress((void**)&p_idx,  g_idx);
    cudaGetSymbolAddress((void**)&p_YZ,   g_YZ);
    cudaGetSymbolAddress((void**)&p_W,    g_W);
    cudaGetSymbolAddress((void**)&p_sq,   g_sq);
    cudaGetSymbolAddress((void**)&p_pmax, g_pmax);
    cudaGetSymbolAddress((void**)&p_psum, g_psum);
    cudaGetSymbolAddress((void**)&p_pool, g_pool);
    cudaGetSymbolAddress((void**)&p_fc1,  g_fc1);
    cudaGetSymbolAddress((void**)&p_fc2,  g_fc2);
    cudaGetSymbolAddress((void**)&p_Ahi,  g_Ahi);
    cudaGetSymbolAddress((void**)&p_Alo,  g_Alo);
    cudaGetSymbolAddress((void**)&p_Bhi,  g_Bhi);
    cudaGetSymbolAddress((void**)&p_Blo,  g_Blo);
    cudaGetSymbolAddress((void**)&p_Xhi,  g_Xhi);
    cudaGetSymbolAddress((void**)&p_Xlo,  g_Xlo);

    static cudaStream_t s_side = nullptr;
    static cudaEvent_t evf[4], evj[4], evW0, evW;
    if (!s_side) {
        cudaStreamCreateWithFlags(&s_side, cudaStreamNonBlocking);
        for (int i = 0; i < 4; ++i) {
            cudaEventCreateWithFlags(&evf[i], cudaEventDisableTiming);
            cudaEventCreateWithFlags(&evj[i], cudaEventDisableTiming);
        }
        cudaEventCreateWithFlags(&evW0, cudaEventDisableTiming);
        cudaEventCreateWithFlags(&evW, cudaEventDisableTiming);
    }

    // side stream: convert w5 to split bf16
    cudaEventRecord(evW0, 0);
    cudaStreamWaitEvent(s_side, evW0, 0);
    cvt_split4_kernel<<<(1024 * 512 / 4 + 255) / 256, 256, 0, s_side>>>(
        w5, p_Bhi, p_Blo, 1024 * 512 / 4);
    cudaEventRecord(evW, s_side);

    // x -> xT fp32 + Xhi/Xlo bf16 + sq, all fused
    {
        int tot = BATCH * NPTS;
        transpose_x_split_kernel<<<(tot + 255) / 256, 256>>>(x, p_xT, p_Xhi, p_Xlo, p_sq);
    }

    struct Blk {
        const float* h; int lda, C, Cpad, O;
        const unsigned short *hhi, *hlo; int hld, Kmma;
        const float* w; const float* bn; int catoff;
    };
    Blk blks[4] = {
        { p_xT,         8,   3,   8,   64,  p_Xhi,       p_Xlo,       32,  32,  w1, bn1, 0   },
        { p_hcat + 0,   512, 64,  64,  64,  p_Ahi,       p_Alo,       512, 64,  w2, bn2, 64  },
        { p_hcat + 64,  512, 64,  64,  128, p_Ahi + 64,  p_Alo + 64,  512, 64,  w3, bn3, 128 },
        { p_hcat + 128, 512, 128, 128, 256, p_Ahi + 128, p_Alo + 128, 512, 128, w4, bn4, 256 },
    };

    for (int i = 0; i < 4; ++i) {
        const Blk& B = blks[i];

        // fork: side stream does prep_w + YZ GEMM
        cudaEventRecord(evf[i], 0);
        cudaStreamWaitEvent(s_side, evf[i], 0);
        {
            int tot = 2 * B.O * B.Cpad;
            prep_w_kernel<<<(tot + 255) / 256, 256, 0, s_side>>>(B.w, p_W, B.O, B.C, B.Cpad);
            dim3 grid((2 * B.O) / 128, (BATCH * NPTS) / 128, 1);
            sgemm_nt_kernel<<<grid, 256, 0, s_side>>>(B.h, p_W, p_YZ,
                BATCH * NPTS, 2 * B.O, B.Cpad, B.lda, B.Cpad, 2 * B.O);
            cudaEventRecord(evj[i], s_side);
        }

        // main: pd via split-bf16 MMA Gram, then topk
        {
            dim3 grid(8, 8, BATCH);
            gram_mma_kernel<<<grid, 256>>>(B.hhi, B.hlo, B.hld, B.Kmma, p_sq, p_pd);
        }
        topk_warp_kernel<<<(BATCH * NPTS) / 8, 256>>>(p_pd, p_idx);

        // join, then fused gather
        cudaStreamWaitEvent(0, evj[i], 0);
        {
            dim3 blk(B.O / 4, 8);
            gather_fused_kernel<<<dim3(NPTS / 8, BATCH), blk>>>(
                p_YZ, p_idx, B.bn, p_hcat, p_Ahi, p_Alo, p_sq,
                B.O, B.catoff, i < 3 ? 1 : 0);
        }
    }

    // conv5 tensor-core GEMM + fused pooling
    cudaStreamWaitEvent(0, evW, 0);
    {
        dim3 grid(8, 128);
        conv5_mma_kernel<<<grid, 256>>>(p_Ahi, p_Alo, p_Bhi, p_Blo, bn5, p_pmax, p_psum);
    }
    {
        int tot = BATCH * 1024;
        pool_reduce_kernel<<<(tot + 255) / 256, 256>>>(p_pmax, p_psum, p_pool);
    }

    {
        int warps = BATCH * 512;
        fc_kernel<<<(warps * 32 + 255) / 256, 256>>>(p_pool, wl1, bn6, nullptr,
                                                     p_fc1, 512, 2048, BATCH);
    }
    {
        int warps = BATCH * 256;
        fc_kernel<<<(warps * 32 + 255) / 256, 256>>>(p_fc1, wl2, bn7, nullptr,
                                                     p_fc2, 256, 512, BATCH);
    }
    {
        int warps = BATCH * 40;
        fc_kernel<<<(warps * 32 + 255) / 256, 256>>>(p_fc2, wl3, nullptr, bl3,
                                                     out, 40, 256, BATCH);
    }
}

// round 14
// speedup vs baseline: 1.0000x; 1.0000x over previous
#include <cuda_runtime.h>
#include <cuda_bf16.h>
#include <cmath>

#define BATCH 16
#define NPTS  1024
#define KNN   20
#define EPSBN 1e-5f
#define SLOPE 0.2f

// ---------------- scratch (device globals; no allocations allowed) ----------------
__device__ float g_xT[BATCH * NPTS * 8];
__device__ float g_hcat[BATCH * NPTS * 512];
__device__ unsigned g_pd[(long long)BATCH * NPTS * NPTS];   // monotone keys
__device__ int   g_idx[BATCH * NPTS * KNN];
__device__ float g_YZ[BATCH * NPTS * 512];
__device__ float g_W[512 * 128];
__device__ float g_sq[BATCH * NPTS];
__device__ float g_pmax[8 * BATCH * 1024];
__device__ float g_psum[8 * BATCH * 1024];
__device__ float g_pool[BATCH * 2048];
__device__ float g_fc1[BATCH * 512];
__device__ float g_fc2[BATCH * 256];
// split-bf16 buffers
__device__ unsigned short g_Ahi[BATCH * NPTS * 512];
__device__ unsigned short g_Alo[BATCH * NPTS * 512];
__device__ unsigned short g_Bhi[1024 * 512];
__device__ unsigned short g_Blo[1024 * 512];
__device__ unsigned short g_Xhi[BATCH * NPTS * 32];
__device__ unsigned short g_Xlo[BATCH * NPTS * 32];

// ---------------- helpers ----------------
__device__ __forceinline__ unsigned long long pack2(float lo, float hi)
{
    unsigned long long r;
    asm("mov.b64 %0, {%1, %2};" : "=l"(r) : "f"(lo), "f"(hi));
    return r;
}
__device__ __forceinline__ void ffma2(unsigned long long& acc,
                                      unsigned long long a, unsigned long long b)
{
    asm("fma.rn.f32x2 %0, %1, %2, %0;" : "+l"(acc) : "l"(a), "l"(b));
}
__device__ __forceinline__ float2 unpack2(unsigned long long v)
{
    float lo, hi;
    asm("mov.b64 {%0, %1}, %2;" : "=f"(lo), "=f"(hi) : "l"(v));
    return make_float2(lo, hi);
}
__device__ __forceinline__ void mma_bf16(float* d, const unsigned* a, const unsigned* b)
{
    asm volatile(
        "mma.sync.aligned.m16n8k16.row.col.f32.bf16.bf16.f32 "
        "{%0,%1,%2,%3}, {%4,%5,%6,%7}, {%8,%9}, {%0,%1,%2,%3};"
        : "+f"(d[0]), "+f"(d[1]), "+f"(d[2]), "+f"(d[3])
        : "r"(a[0]), "r"(a[1]), "r"(a[2]), "r"(a[3]), "r"(b[0]), "r"(b[1]));
}
__device__ __forceinline__ unsigned short bf_bits(__nv_bfloat16 h)
{
    unsigned short s;
    memcpy(&s, &h, 2);
    return s;
}
__device__ __forceinline__ unsigned pk16(unsigned short a, unsigned short b)
{
    return (unsigned)a | ((unsigned)b << 16);
}
__device__ __forceinline__ unsigned fkey(float f)
{
    unsigned u = __float_as_uint(f);
    return (u & 0x80000000u) ? ~u : (u | 0x80000000u);
}

// ---------------- transpose x + split bf16 + sq, all fused ----------------
__global__ void transpose_x_split_kernel(const float* __restrict__ x,
                                         float* __restrict__ xT,
                                         unsigned short* __restrict__ Xhi,
                                         unsigned short* __restrict__ Xlo,
                                         float* __restrict__ sq)
{
    int p = blockIdx.x * blockDim.x + threadIdx.x;
    if (p >= BATCH * NPTS) return;
    int b = p / NPTS;
    int n = p % NPTS;
    const float* xb = x + (long long)b * 3 * NPTS + n;
    float v0 = xb[0], v1 = xb[NPTS], v2 = xb[2 * NPTS];
    *(float4*)&xT[p * 8]     = make_float4(v0, v1, v2, 0.f);
    *(float4*)&xT[p * 8 + 4] = make_float4(0.f, 0.f, 0.f, 0.f);
    sq[p] = v0 * v0 + v1 * v1 + v2 * v2;

    __nv_bfloat16 h0 = __float2bfloat16_rn(v0);
    __nv_bfloat16 h1 = __float2bfloat16_rn(v1);
    __nv_bfloat16 h2 = __float2bfloat16_rn(v2);
    __nv_bfloat16 l0 = __float2bfloat16_rn(v0 - __bfloat162float(h0));
    __nv_bfloat16 l1 = __float2bfloat16_rn(v1 - __bfloat162float(h1));
    __nv_bfloat16 l2 = __float2bfloat16_rn(v2 - __bfloat162float(h2));

    uint4 z = make_uint4(0, 0, 0, 0);
    uint4 vh = make_uint4(pk16(bf_bits(h0), bf_bits(h1)), pk16(bf_bits(h2), 0), 0, 0);
    uint4 vl = make_uint4(pk16(bf_bits(l0), bf_bits(l1)), pk16(bf_bits(l2), 0), 0, 0);
    uint4* ph = (uint4*)(Xhi + p * 32);
    uint4* pl = (uint4*)(Xlo + p * 32);
    ph[0] = vh; ph[1] = z; ph[2] = z; ph[3] = z;
    pl[0] = vl; pl[1] = z; pl[2] = z; pl[3] = z;
}

// ---------------- fp32 -> (hi, lo) bf16 split (w5) ----------------
__global__ void cvt_split4_kernel(const float* __restrict__ in,
                                  unsigned short* __restrict__ hi,
                                  unsigned short* __restrict__ lo, int n4)
{
    int i = blockIdx.x * blockDim.x + threadIdx.x;
    if (i >= n4) return;
    float4 v = ((const float4*)in)[i];
    __nv_bfloat16 h0 = __float2bfloat16_rn(v.x);
    __nv_bfloat16 h1 = __float2bfloat16_rn(v.y);
    __nv_bfloat16 h2 = __float2bfloat16_rn(v.z);
    __nv_bfloat16 h3 = __float2bfloat16_rn(v.w);
    __nv_bfloat16 l0 = __float2bfloat16_rn(v.x - __bfloat162float(h0));
    __nv_bfloat16 l1 = __float2bfloat16_rn(v.y - __bfloat162float(h1));
    __nv_bfloat16 l2 = __float2bfloat16_rn(v.z - __bfloat162float(h2));
    __nv_bfloat16 l3 = __float2bfloat16_rn(v.w - __bfloat162float(h3));
    uint2* hp = (uint2*)(hi + i * 4);
    uint2* lp = (uint2*)(lo + i * 4);
    *hp = make_uint2(pk16(bf_bits(h0), bf_bits(h1)), pk16(bf_bits(h2), bf_bits(h3)));
    *lp = make_uint2(pk16(bf_bits(l0), bf_bits(l1)), pk16(bf_bits(l2), bf_bits(l3)));
}

// ---------------- split-bf16 MMA Gram -> monotone keys --------------------------
// pd keys: key(2*H@H^T - sq_m - sq_n); ordering identical to float pd.
__global__ void __launch_bounds__(256)
gram_mma_kernel(const unsigned short* __restrict__ Hhi,
                const unsigned short* __restrict__ Hlo,
                int ld, int K,
                const float* __restrict__ sq, unsigned* __restrict__ pd)
{
    __shared__ __align__(16) unsigned sah[128 * 20], sal[128 * 20],
                                      sbh[128 * 20], sbl[128 * 20];

    int b = blockIdx.z;
    long long hbase = (long long)b * NPTS * ld;
    const float* sqb = sq + b * NPTS;
    unsigned* pdb = pd + (long long)b * NPTS * NPTS;

    int tid = threadIdx.x;
    int lane = tid & 31;
    int w = tid >> 5;
    int wm = w & 1, wn = w >> 1;
    int gr = lane >> 2, tig = lane & 3;
    int bx = blockIdx.x, by = blockIdx.y;

    int l_row = tid >> 1;
    int q0 = (tid & 1) * 2;
    long long a_base = hbase + (long long)(by * 128 + l_row) * ld;
    long long b_base = hbase + (long long)(bx * 128 + l_row) * ld;

    int nk = K >> 5;

    uint4 pa_h[2], pa_l[2], pb_h[2], pb_l[2];
    #pragma unroll
    for (int q = 0; q < 2; ++q) {
        pa_h[q] = *(const uint4*)(Hhi + a_base + (q0 + q) * 8);
        pa_l[q] = *(const uint4*)(Hlo + a_base + (q0 + q) * 8);
        pb_h[q] = *(const uint4*)(Hhi + b_base + (q0 + q) * 8);
        pb_l[q] = *(const uint4*)(Hlo + b_base + (q0 + q) * 8);
    }

    float acc[4][4][4];
    #pragma unroll
    for (int mt = 0; mt < 4; ++mt)
        #pragma unroll
        for (int nt = 0; nt < 4; ++nt)
            #pragma unroll
            for (int c = 0; c < 4; ++c)
                acc[mt][nt][c] = 0.f;

    for (int kt = 0; kt < nk; ++kt) {
        #pragma unroll
        for (int q = 0; q < 2; ++q) {
            *(uint4*)&sah[l_row * 20 + (q0 + q) * 4] = pa_h[q];
            *(uint4*)&sal[l_row * 20 + (q0 + q) * 4] = pa_l[q];
            *(uint4*)&sbh[l_row * 20 + (q0 + q) * 4] = pb_h[q];
            *(uint4*)&sbl[l_row * 20 + (q0 + q) * 4] = pb_l[q];
        }
        __syncthreads();

        if (kt + 1 < nk) {
            long long koff = (long long)(kt + 1) * 32;
            #pragma unroll
            for (int q = 0; q < 2; ++q) {
                pa_h[q] = *(const uint4*)(Hhi + a_base + koff + (q0 + q) * 8);
                pa_l[q] = *(const uint4*)(Hlo + a_base + koff + (q0 + q) * 8);
                pb_h[q] = *(const uint4*)(Hhi + b_base + koff + (q0 + q) * 8);
                pb_l[q] = *(const uint4*)(Hlo + b_base + koff + (q0 + q) * 8);
            }
        }

        #pragma unroll
        for (int s = 0; s < 2; ++s) {
            unsigned ahf[4][4], alf[4][4];
            #pragma unroll
            for (int mt = 0; mt < 4; ++mt) {
                int r0 = wm * 64 + mt * 16 + gr;
                int p = s * 8 + tig;
                ahf[mt][0] = sah[r0 * 20 + p];
                ahf[mt][1] = sah[(r0 + 8) * 20 + p];
                ahf[mt][2] = sah[r0 * 20 + p + 4];
                ahf[mt][3] = sah[(r0 + 8) * 20 + p + 4];
                alf[mt][0] = sal[r0 * 20 + p];
                alf[mt][1] = sal[(r0 + 8) * 20 + p];
                alf[mt][2] = sal[r0 * 20 + p + 4];
                alf[mt][3] = sal[(r0 + 8) * 20 + p + 4];
            }
            unsigned bhf[4][2], blf[4][2];
            #pragma unroll
            for (int nt = 0; nt < 4; ++nt) {
                int n0 = wn * 32 + nt * 8 + gr;
                int p = s * 8 + tig;
                bhf[nt][0] = sbh[n0 * 20 + p];
                bhf[nt][1] = sbh[n0 * 20 + p + 4];
                blf[nt][0] = sbl[n0 * 20 + p];
                blf[nt][1] = sbl[n0 * 20 + p + 4];
            }
            #pragma unroll
            for (int mt = 0; mt < 4; ++mt)
                #pragma unroll
                for (int nt = 0; nt < 4; ++nt) {
                    mma_bf16(acc[mt][nt], ahf[mt], bhf[nt]);
                    mma_bf16(acc[mt][nt], ahf[mt], blf[nt]);
                    mma_bf16(acc[mt][nt], alf[mt], bhf[nt]);
                }
        }
        __syncthreads();
    }

    #pragma unroll
    for (int mt = 0; mt < 4; ++mt) {
        int r0 = by * 128 + wm * 64 + mt * 16 + gr;
        float sq0 = sqb[r0];
        float sq1 = sqb[r0 + 8];
        #pragma unroll
        for (int nt = 0; nt < 4; ++nt) {
            int c = bx * 128 + wn * 32 + nt * 8 + 2 * tig;
            float sc0 = sqb[c], sc1 = sqb[c + 1];
            *(uint2*)&pdb[(long long)r0 * NPTS + c] =
                make_uint2(fkey(2.f * acc[mt][nt][0] - sq0 - sc0),
                           fkey(2.f * acc[mt][nt][1] - sq0 - sc1));
            *(uint2*)&pdb[(long long)(r0 + 8) * NPTS + c] =
                make_uint2(fkey(2.f * acc[mt][nt][2] - sq1 - sc0),
                           fkey(2.f * acc[mt][nt][3] - sq1 - sc1));
        }
    }
}

// ---------------- 128x128 tiled SGEMM, f32x2 core (YZ GEMM) ----------------
__global__ void __launch_bounds__(256)
sgemm_nt_kernel(const float* __restrict__ A, const float* __restrict__ Bw,
                float* __restrict__ C,
                int M, int Nn, int K, int lda, int ldb, int ldc)
{
    __shared__ float As[8][128];
    __shared__ float Bs[8][128];

    int tid = threadIdx.x;
    int tx = tid & 15;
    int ty = tid >> 4;
    int bx = blockIdx.x, by = blockIdx.y;

    int l_row = tid >> 1;
    int l_k0  = (tid & 1) * 4;

    const float* aptr = A + (long long)(by * 128 + l_row) * lda + l_k0;
    const float* bptr = Bw + (long long)(bx * 128 + l_row) * ldb + l_k0;

    float4 ra = *(const float4*)aptr;
    float4 rb = *(const float4*)bptr;

    unsigned long long acc2[8][4];
    #pragma unroll
    for (int i = 0; i < 8; ++i)
        #pragma unroll
        for (int j = 0; j < 4; ++j)
            acc2[i][j] = 0ull;

    for (int kt = 0; kt < K; kt += 8) {
        As[l_k0 + 0][l_row] = ra.x;
        As[l_k0 + 1][l_row] = ra.y;
        As[l_k0 + 2][l_row] = ra.z;
        As[l_k0 + 3][l_row] = ra.w;
        Bs[l_k0 + 0][l_row] = rb.x;
        Bs[l_k0 + 1][l_row] = rb.y;
        Bs[l_k0 + 2][l_row] = rb.z;
        Bs[l_k0 + 3][l_row] = rb.w;
        __syncthreads();

        if (kt + 8 < K) {
            ra = *(const float4*)(aptr + kt + 8);
            rb = *(const float4*)(bptr + kt + 8);
        }

        #pragma unroll
        for (int kk = 0; kk < 8; ++kk) {
            float4 a0 = *(const float4*)&As[kk][ty * 8];
            float4 a1 = *(const float4*)&As[kk][ty * 8 + 4];
            float4 b0 = *(const float4*)&Bs[kk][tx * 8];
            float4 b1 = *(const float4*)&Bs[kk][tx * 8 + 4];

            unsigned long long bp[4];
            bp[0] = pack2(b0.x, b0.y);
            bp[1] = pack2(b0.z, b0.w);
            bp[2] = pack2(b1.x, b1.y);
            bp[3] = pack2(b1.z, b1.w);

            float a[8] = {a0.x, a0.y, a0.z, a0.w, a1.x, a1.y, a1.z, a1.w};
            #pragma unroll
            for (int i = 0; i < 8; ++i) {
                unsigned long long ap = pack2(a[i], a[i]);
                #pragma unroll
                for (int j = 0; j < 4; ++j)
                    ffma2(acc2[i][j], ap, bp[j]);
            }
        }
        __syncthreads();
    }

    #pragma unroll
    for (int i = 0; i < 8; ++i) {
        int gm = by * 128 + ty * 8 + i;
        #pragma unroll
        for (int jj = 0; jj < 2; ++jj) {
            float4 v4;
            float2 p0 = unpack2(acc2[i][jj * 2]);
            float2 p1 = unpack2(acc2[i][jj * 2 + 1]);
            v4.x = p0.x; v4.y = p0.y; v4.z = p1.x; v4.w = p1.y;
            *(float4*)&C[(long long)gm * ldc + bx * 128 + tx * 8 + jj * 4] = v4;
        }
    }
}

// ---------------- conv5 split-bf16 MMA + fused BN/LReLU + pooling ---------------
__global__ void __launch_bounds__(256)
conv5_mma_kernel(const unsigned short* __restrict__ Ahi, const unsigned short* __restrict__ Alo,
                 const unsigned short* __restrict__ Bhi, const unsigned short* __restrict__ Blo,
                 const float* __restrict__ bn,
                 float* __restrict__ pmax, float* __restrict__ psum)
{
    __shared__ __align__(16) union SM {
        struct { unsigned ah[128 * 20], al[128 * 20], bh[128 * 20], bl[128 * 20]; } t;
        struct { float rmax[2][128]; float rsum[2][128]; } r;
    } sm;

    int tid = threadIdx.x;
    int lane = tid & 31;
    int w = tid >> 5;
    int wm = w & 1, wn = w >> 1;
    int gr = lane >> 2, tig = lane & 3;
    int bx = blockIdx.x, by = blockIdx.y;

    int l_row = tid >> 1;
    int q0 = (tid & 1) * 2;
    long long a_base = (long long)(by * 128 + l_row) * 512;
    long long b_base = (long long)(bx * 128 + l_row) * 512;

    uint4 pa_h[2], pa_l[2], pb_h[2], pb_l[2];
    #pragma unroll
    for (int q = 0; q < 2; ++q) {
        pa_h[q] = *(const uint4*)(Ahi + a_base + (q0 + q) * 8);
        pa_l[q] = *(const uint4*)(Alo + a_base + (q0 + q) * 8);
        pb_h[q] = *(const uint4*)(Bhi + b_base + (q0 + q) * 8);
        pb_l[q] = *(const uint4*)(Blo + b_base + (q0 + q) * 8);
    }

    float acc[4][4][4];
    #pragma unroll
    for (int mt = 0; mt < 4; ++mt)
        #pragma unroll
        for (int nt = 0; nt < 4; ++nt)
            #pragma unroll
            for (int c = 0; c < 4; ++c)
                acc[mt][nt][c] = 0.f;

    for (int kt = 0; kt < 16; ++kt) {
        #pragma unroll
        for (int q = 0; q < 2; ++q) {
            *(uint4*)&sm.t.ah[l_row * 20 + (q0 + q) * 4] = pa_h[q];
            *(uint4*)&sm.t.al[l_row * 20 + (q0 + q) * 4] = pa_l[q];
            *(uint4*)&sm.t.bh[l_row * 20 + (q0 + q) * 4] = pb_h[q];
            *(uint4*)&sm.t.bl[l_row * 20 + (q0 + q) * 4] = pb_l[q];
        }
        __syncthreads();

        if (kt + 1 < 16) {
            long long koff = (long long)(kt + 1) * 32;
            #pragma unroll
            for (int q = 0; q < 2; ++q) {
                pa_h[q] = *(const uint4*)(Ahi + a_base + koff + (q0 + q) * 8);
                pa_l[q] = *(const uint4*)(Alo + a_base + koff + (q0 + q) * 8);
                pb_h[q] = *(const uint4*)(Bhi + b_base + koff + (q0 + q) * 8);
                pb_l[q] = *(const uint4*)(Blo + b_base + koff + (q0 + q) * 8);
            }
        }

        #pragma unroll
        for (int s = 0; s < 2; ++s) {
            unsigned ahf[4][4], alf[4][4];
            #pragma unroll
            for (int mt = 0; mt < 4; ++mt) {
                int r0 = wm * 64 + mt * 16 + gr;
                int p = s * 8 + tig;
                ahf[mt][0] = sm.t.ah[r0 * 20 + p];
                ahf[mt][1] = sm.t.ah[(r0 + 8) * 20 + p];
                ahf[mt][2] = sm.t.ah[r0 * 20 + p + 4];
                ahf[mt][3] = sm.t.ah[(r0 + 8) * 20 + p + 4];
                alf[mt][0] = sm.t.al[r0 * 20 + p];
                alf[mt][1] = sm.t.al[(r0 + 8) * 20 + p];
                alf[mt][2] = sm.t.al[r0 * 20 + p + 4];
                alf[mt][3] = sm.t.al[(r0 + 8) * 20 + p + 4];
            }
            unsigned bhf[4][2], blf[4][2];
            #pragma unroll
            for (int nt = 0; nt < 4; ++nt) {
                int n0 = wn * 32 + nt * 8 + gr;
                int p = s * 8 + tig;
                bhf[nt][0] = sm.t.bh[n0 * 20 + p];
                bhf[nt][1] = sm.t.bh[n0 * 20 + p + 4];
                blf[nt][0] = sm.t.bl[n0 * 20 + p];
                blf[nt][1] = sm.t.bl[n0 * 20 + p + 4];
            }
            #pragma unroll
            for (int mt = 0; mt < 4; ++mt)
                #pragma unroll
                for (int nt = 0; nt < 4; ++nt) {
                    mma_bf16(acc[mt][nt], ahf[mt], bhf[nt]);
                    mma_bf16(acc[mt][nt], ahf[mt], blf[nt]);
                    mma_bf16(acc[mt][nt], alf[mt], bhf[nt]);
                }
        }
        __syncthreads();
    }

    #pragma unroll
    for (int nt = 0; nt < 4; ++nt) {
        #pragma unroll
        for (int j = 0; j < 2; ++j) {
            int lcol = wn * 32 + nt * 8 + 2 * tig + j;
            int col = bx * 128 + lcol;
            float g  = bn[col];
            float be = bn[1024 + col];
            float mu = bn[2048 + col];
            float va = bn[3072 + col];
            float s = g * rsqrtf(va + EPSBN);
            float o = be - mu * s;
            float mx = -INFINITY, smv = 0.f;
            #pragma unroll
            for (int mt = 0; mt < 4; ++mt) {
                float v0 = s * acc[mt][nt][j] + o;
                v0 = v0 > 0.f ? v0 : SLOPE * v0;
                float v1 = s * acc[mt][nt][2 + j] + o;
                v1 = v1 > 0.f ? v1 : SLOPE * v1;
                mx = fmaxf(mx, fmaxf(v0, v1));
                smv += v0 + v1;
            }
            #pragma unroll
            for (int off = 4; off <= 16; off <<= 1) {
                mx = fmaxf(mx, __shfl_xor_sync(0xffffffffu, mx, off));
                smv += __shfl_xor_sync(0xffffffffu, smv, off);
            }
            if (gr == 0) {
                sm.r.rmax[wm][lcol] = mx;
                sm.r.rsum[wm][lcol] = smv;
            }
        }
    }
    __syncthreads();

    if (tid < 128) {
        int c = tid;
        float mx = fmaxf(sm.r.rmax[0][c], sm.r.rmax[1][c]);
        float s2 = sm.r.rsum[0][c] + sm.r.rsum[1][c];
        int b = by >> 3, chunk = by & 7;
        pmax[((long long)chunk * BATCH + b) * 1024 + bx * 128 + c] = mx;
        psum[((long long)chunk * BATCH + b) * 1024 + bx * 128 + c] = s2;
    }
}

// ---------------- final pool reduce over 8 chunks ----------------
__global__ void pool_reduce_kernel(const float* __restrict__ pmax,
                                   const float* __restrict__ psum,
                                   float* __restrict__ pool)
{
    int gi = blockIdx.x * blockDim.x + threadIdx.x;
    if (gi >= BATCH * 1024) return;
    int b = gi >> 10;
    int c = gi & 1023;
    float mx = -INFINITY, sm = 0.f;
    #pragma unroll
    for (int chunk = 0; chunk < 8; ++chunk) {
        mx = fmaxf(mx, pmax[((long long)chunk * BATCH + b) * 1024 + c]);
        sm += psum[((long long)chunk * BATCH + b) * 1024 + c];
    }
    pool[b * 2048 + c] = mx;
    pool[b * 2048 + 1024 + c] = sm * (1.f / (float)NPTS);
}

// ---------------- warp-per-row top-k (k=20), REDUX + sorted top-4 cache ---------
// pd already holds monotone keys; no conversion needed.
__global__ void __launch_bounds__(256) topk_warp_kernel(const unsigned* __restrict__ pd,
                                                        int* __restrict__ out)
{
    int warp_in_blk = threadIdx.x >> 5;
    int lane = threadIdx.x & 31;
    int row = blockIdx.x * 8 + warp_in_blk;

    const unsigned* __restrict__ p = pd + (long long)row * NPTS;

    unsigned k[32];
    #pragma unroll
    for (int j = 0; j < 32; ++j)
        k[j] = p[j * 32 + lane];

    unsigned c0 = 0, c1 = 0, c2 = 0, c3 = 0;
    int i0 = 0, i1 = 0, i2 = 0, i3 = 0;
    #pragma unroll
    for (int j = 0; j < 32; ++j) {
        unsigned v = k[j];
        if (v > c3) {
            if (v > c2) {
                if (v > c1) {
                    if (v > c0) { c3=c2;i3=i2; c2=c1;i2=i1; c1=c0;i1=i0; c0=v;i0=j; }
                    else        { c3=c2;i3=i2; c2=c1;i2=i1; c1=v;i1=j; }
                } else          { c3=c2;i3=i2; c2=v;i2=j; }
            } else              { c3=v;i3=j; }
        }
    }

    int* __restrict__ o = out + (long long)row * KNN;

    #pragma unroll 1
    for (int it = 0; it < KNN; ++it) {
        unsigned m = __reduce_max_sync(0xffffffffu, c0);
        unsigned bal = __ballot_sync(0xffffffffu, c0 == m);
        int src = __ffs((int)bal) - 1;
        int gi = __shfl_sync(0xffffffffu, (i0 << 5) | lane, src);
        if (lane == 0) o[it] = gi;

        if (lane == src) {
            k[i0] = 0u;
            c0 = c1; i0 = i1;
            c1 = c2; i1 = i2;
            c2 = c3; i2 = i3;
            c3 = 0;  i3 = 0;
            if (c0 == 0u) {
                #pragma unroll
                for (int j = 0; j < 32; ++j) {
                    unsigned v = k[j];
                    if (v > c3) {
                        if (v > c2) {
                            if (v > c1) {
                                if (v > c0) { c3=c2;i3=i2; c2=c1;i2=i1; c1=c0;i1=i0; c0=v;i0=j; }
                                else        { c3=c2;i3=i2; c2=c1;i2=i1; c1=v;i1=j; }
                            } else          { c3=c2;i3=i2; c2=v;i2=j; }
                        } else              { c3=v;i3=j; }
                    }
                }
            }
        }
    }
}

// ---------------- prepare edge weights: [wa ; wb - wa], K-padded ----------------
__global__ void prep_w_kernel(const float* __restrict__ w, float* __restrict__ Wc,
                              int O, int C, int Cpad)
{
    int i = blockIdx.x * blockDim.x + threadIdx.x;
    int tot = 2 * O * Cpad;
    if (i >= tot) return;
    int half = i / (O * Cpad);
    int j = i % (O * Cpad);
    int o = j / Cpad, c = j % Cpad;
    float v = 0.f;
    if (c < C)
        v = half == 0 ? w[o * 2 * C + c]
                      : w[o * 2 * C + C + c] - w[o * 2 * C + c];
    Wc[half * O * Cpad + o * Cpad + c] = v;
}

// ---------------- FUSED gather + max_k + BN + LReLU + bf16 split + sq -----------
__global__ void gather_fused_kernel(const float* __restrict__ YZ,
                                    const int* __restrict__ idx,
                                    const float* __restrict__ bn,
                                    float* __restrict__ hcat,
                                    unsigned short* __restrict__ Ahi,
                                    unsigned short* __restrict__ Alo,
                                    float* __restrict__ sq,
                                    int O, int catoff, int writeSq)
{
    int b = blockIdx.y;
    int n0 = blockIdx.x * 8;
    int o4 = threadIdx.x;
    int py = threadIdx.y;
    int n = n0 + py;

    __shared__ int sidx[8][KNN];
    __shared__ float ssq[8][64];
    int bw = blockDim.x * 8;
    for (int t = threadIdx.y * blockDim.x + threadIdx.x; t < 8 * KNN; t += bw)
        sidx[t / KNN][t % KNN] = idx[((long long)b * NPTS + n0 + t / KNN) * KNN + t % KNN];
    __syncthreads();

    int ld = 2 * O;
    const float* base = YZ + (long long)b * NPTS * ld;

    float4 zc = *(const float4*)&base[(long long)n * ld + O + o4 * 4];
    float4 mx = make_float4(-INFINITY, -INFINITY, -INFINITY, -INFINITY);
    float4 mn = make_float4(INFINITY, INFINITY, INFINITY, INFINITY);
    #pragma unroll
    for (int kk = 0; kk < KNN; ++kk) {
        float4 y = *(const float4*)&base[(long long)sidx[py][kk] * ld + o4 * 4];
        mx.x = fmaxf(mx.x, y.x); mn.x = fminf(mn.x, y.x);
        mx.y = fmaxf(mx.y, y.y); mn.y = fminf(mn.y, y.y);
        mx.z = fmaxf(mx.z, y.z); mn.z = fminf(mn.z, y.z);
        mx.w = fmaxf(mx.w, y.w); mn.w = fminf(mn.w, y.w);
    }

    float4 g4  = *(const float4*)&bn[o4 * 4];
    float4 be4 = *(const float4*)&bn[O + o4 * 4];
    float4 mu4 = *(const float4*)&bn[2 * O + o4 * 4];
    float4 va4 = *(const float4*)&bn[3 * O + o4 * 4];

    float4 r;
    {
        float s = g4.x * rsqrtf(va4.x + EPSBN);
        float z = (s >= 0.f ? mx.x : mn.x) + zc.x;
        float v = s * z + (be4.x - mu4.x * s);
        r.x = v > 0.f ? v : SLOPE * v;
    }
    {
        float s = g4.y * rsqrtf(va4.y + EPSBN);
        float z = (s >= 0.f ? mx.y : mn.y) + zc.y;
        float v = s * z + (be4.y - mu4.y * s);
        r.y = v > 0.f ? v : SLOPE * v;
    }
    {
        float s = g4.z * rsqrtf(va4.z + EPSBN);
        float z = (s >= 0.f ? mx.z : mn.z) + zc.z;
        float v = s * z + (be4.z - mu4.z * s);
        r.z = v > 0.f ? v : SLOPE * v;
    }
    {
        float s = g4.w * rsqrtf(va4.w + EPSBN);
        float z = (s >= 0.f ? mx.w : mn.w) + zc.w;
        float v = s * z + (be4.w - mu4.w * s);
        r.w = v > 0.f ? v : SLOPE * v;
    }

    long long off = ((long long)b * NPTS + n) * 512 + catoff + o4 * 4;
    *(float4*)&hcat[off] = r;

    __nv_bfloat16 h0 = __float2bfloat16_rn(r.x);
    __nv_bfloat16 h1 = __float2bfloat16_rn(r.y);
    __nv_bfloat16 h2 = __float2bfloat16_rn(r.z);
    __nv_bfloat16 h3 = __float2bfloat16_rn(r.w);
    __nv_bfloat16 l0 = __float2bfloat16_rn(r.x - __bfloat162float(h0));
    __nv_bfloat16 l1 = __float2bfloat16_rn(r.y - __bfloat162float(h1));
    __nv_bfloat16 l2 = __float2bfloat16_rn(r.z - __bfloat162float(h2));
    __nv_bfloat16 l3 = __float2bfloat16_rn(r.w - __bfloat162float(h3));
    *(uint2*)(Ahi + off) = make_uint2(pk16(bf_bits(h0), bf_bits(h1)),
                                      pk16(bf_bits(h2), bf_bits(h3)));
    *(uint2*)(Alo + off) = make_uint2(pk16(bf_bits(l0), bf_bits(l1)),
                                      pk16(bf_bits(l2), bf_bits(l3)));

    if (writeSq) {
        ssq[py][o4] = r.x * r.x + r.y * r.y + r.z * r.z + r.w * r.w;
        __syncthreads();
        if (o4 == 0) {
            float s = 0.f;
            for (int j = 0; j < blockDim.x; ++j) s += ssq[py][j];
            sq[(long long)b * NPTS + n] = s;
        }
    }
}

// ---------------- FC layer: warp per (b,o) ----------------
__global__ void fc_kernel(const float* __restrict__ in, const float* __restrict__ W,
                          const float* __restrict__ bn, const float* __restrict__ bias,
                          float* __restrict__ out, int O, int K, int Bn)
{
    int gw = (blockIdx.x * blockDim.x + threadIdx.x) >> 5;
    int lane = threadIdx.x & 31;
    if (gw >= Bn * O) return;
    int b = gw / O, o = gw % O;
    float acc = 0.f;
    const float* ip = in + (long long)b * K;
    const float* wp = W + (long long)o * K;
    for (int k = lane; k < K; k += 32) acc += ip[k] * wp[k];
    #pragma unroll
    for (int off = 16; off > 0; off >>= 1)
        acc += __shfl_down_sync(0xffffffffu, acc, off);
    if (lane == 0) {
        float v = acc;
        if (bn) {
            float g  = bn[o];
            float be = bn[O + o];
            float mu = bn[2 * O + o];
            float va = bn[3 * O + o];
            float s = g * rsqrtf(va + EPSBN);
            v = s * v + (be - mu * s);
            v = v > 0.f ? v : SLOPE * v;
        } else {
            v += bias[o];
        }
        out[(long long)b * O + o] = v;
    }
}

// ---------------- host orchestration (default + 1 side stream) ----------------
extern "C" void kernel_launch(void* const* d_in, const int* in_sizes, int n_in,
                              void* d_out, int out_size)
{
    (void)in_sizes; (void)n_in; (void)out_size;
    const float* x   = (const float*)d_in[0];
    const float* w1  = (const float*)d_in[1];
    const float* bn1 = (const float*)d_in[2];
    const float* w2  = (const float*)d_in[3];
    const float* bn2 = (const float*)d_in[4];
    const float* w3  = (const float*)d_in[5];
    const float* bn3 = (const float*)d_in[6];
    const float* w4  = (const float*)d_in[7];
    const float* bn4 = (const float*)d_in[8];
    const float* w5  = (const float*)d_in[9];
    const float* bn5 = (const float*)d_in[10];
    const float* wl1 = (const float*)d_in[11];
    const float* bn6 = (const float*)d_in[12];
    const float* wl2 = (const float*)d_in[13];
    const float* bn7 = (const float*)d_in[14];
    const float* wl3 = (const float*)d_in[15];
    const float* bl3 = (const float*)d_in[16];
    float* out = (float*)d_out;

    float *p_xT, *p_hcat, *p_YZ, *p_W, *p_sq, *p_pmax, *p_psum,
          *p_pool, *p_fc1, *p_fc2;
    unsigned* p_pd;
    int* p_idx;
    unsigned short *p_Ahi, *p_Alo, *p_Bhi, *p_Blo, *p_Xhi, *p_Xlo;
    cudaGetSymbolAddress((void**)&p_xT,   g_xT);
    cudaGetSymbolAddress((void**)&p_hcat, g_hcat);
    cudaGetSymbolAddress((void**)&p_pd,   g_pd);
    cudaGetSymbolAddress((void**)&p_idx,  g_idx);
    cudaGetSymbolAddress((void**)&p_YZ,   g_YZ);
    cudaGetSymbolAddress((void**)&p_W,    g_W);
    cudaGetSymbolAddress((void**)&p_sq,   g_sq);
    cudaGetSymbolAddress((void**)&p_pmax, g_pmax);
    cudaGetSymbolAddress((void**)&p_psum, g_psum);
    cudaGetSymbolAddress((void**)&p_pool, g_pool);
    cudaGetSymbolAddress((void**)&p_fc1,  g_fc1);
    cudaGetSymbolAddress((void**)&p_fc2,  g_fc2);
    cudaGetSymbolAddress((void**)&p_Ahi,  g_Ahi);
    cudaGetSymbolAddress((void**)&p_Alo,  g_Alo);
    cudaGetSymbolAddress((void**)&p_Bhi,  g_Bhi);
    cudaGetSymbolAddress((void**)&p_Blo,  g_Blo);
    cudaGetSymbolAddress((void**)&p_Xhi,  g_Xhi);
    cudaGetSymbolAddress((void**)&p_Xlo,  g_Xlo);

    static cudaStream_t s_side = nullptr;
    static cudaEvent_t evf[4], evj[4], evW0, evW;
    if (!s_side) {
        cudaStreamCreateWithFlags(&s_side, cudaStreamNonBlocking);
        for (int i = 0; i < 4; ++i) {
            cudaEventCreateWithFlags(&evf[i], cudaEventDisableTiming);
            cudaEventCreateWithFlags(&evj[i], cudaEventDisableTiming);
        }
        cudaEventCreateWithFlags(&evW0, cudaEventDisableTiming);
        cudaEventCreateWithFlags(&evW, cudaEventDisableTiming);
    }

    // side stream: convert w5 to split bf16
    cudaEventRecord(evW0, 0);
    cudaStreamWaitEvent(s_side, evW0, 0);
    cvt_split4_kernel<<<(1024 * 512 / 4 + 255) / 256, 256, 0, s_side>>>(
        w5, p_Bhi, p_Blo, 1024 * 512 / 4);
    cudaEventRecord(evW, s_side);

    // x -> xT fp32 + Xhi/Xlo bf16 + sq, all fused
    {
        int tot = BATCH * NPTS;
        transpose_x_split_kernel<<<(tot + 255) / 256, 256>>>(x, p_xT, p_Xhi, p_Xlo, p_sq);
    }

    struct Blk {
        const float* h; int lda, C, Cpad, O;
        const unsigned short *hhi, *hlo; int hld, Kmma;
        const float* w; const float* bn; int catoff;
    };
    Blk blks[4] = {
        { p_xT,         8,   3,   8,   64,  p_Xhi,       p_Xlo,       32,  32,  w1, bn1, 0   },
        { p_hcat + 0,   512, 64,  64,  64,  p_Ahi,       p_Alo,       512, 64,  w2, bn2, 64  },
        { p_hcat + 64,  512, 64,  64,  128, p_Ahi + 64,  p_Alo + 64,  512, 64,  w3, bn3, 128 },
        { p_hcat + 128, 512, 128, 128, 256, p_Ahi + 128, p_Alo + 128, 512, 128, w4, bn4, 256 },
    };

    for (int i = 0; i < 4; ++i) {
        const Blk& B = blks[i];

        // fork: side stream does prep_w + YZ GEMM
        cudaEventRecord(evf[i], 0);
        cudaStreamWaitEvent(s_side, evf[i], 0);
        {
            int tot = 2 * B.O * B.Cpad;
            prep_w_kernel<<<(tot + 255) / 256, 256, 0, s_side>>>(B.w, p_W, B.O, B.C, B.Cpad);
            dim3 grid((2 * B.O) / 128, (BATCH * NPTS) / 128, 1);
            sgemm_nt_kernel<<<grid, 256, 0, s_side>>>(B.h, p_W, p_YZ,
                BATCH * NPTS, 2 * B.O, B.Cpad, B.lda, B.Cpad, 2 * B.O);
            cudaEventRecord(evj[i], s_side);
        }

        // main: pd keys via split-bf16 MMA Gram, then topk
        {
            dim3 grid(8, 8, BATCH);
            gram_mma_kernel<<<grid, 256>>>(B.hhi, B.hlo, B.hld, B.Kmma, p_sq, p_pd);
        }
        topk_warp_kernel<<<(BATCH * NPTS) / 8, 256>>>(p_pd, p_idx);

        // join, then fused gather
        cudaStreamWaitEvent(0, evj[i], 0);
        {
            dim3 blk(B.O / 4, 8);
            gather_fused_kernel<<<dim3(NPTS / 8, BATCH), blk>>>(
                p_YZ, p_idx, B.bn, p_hcat, p_Ahi, p_Alo, p_sq,
                B.O, B.catoff, i < 3 ? 1 : 0);
        }
    }

    // conv5 tensor-core GEMM + fused pooling
    cudaStreamWaitEvent(0, evW, 0);
    {
        dim3 grid(8, 128);
        conv5_mma_kernel<<<grid, 256>>>(p_Ahi, p_Alo, p_Bhi, p_Blo, bn5, p_pmax, p_psum);
    }
    {
        int tot = BATCH * 1024;
        pool_reduce_kernel<<<(tot + 255) / 256, 256>>>(p_pmax, p_psum, p_pool);
    }

    {
        int warps = BATCH * 512;
        fc_kernel<<<(warps * 32 + 255) / 256, 256>>>(p_pool, wl1, bn6, nullptr,
                                                     p_fc1, 512, 2048, BATCH);
    }
    {
        int warps = BATCH * 256;
        fc_kernel<<<(warps * 32 + 255) / 256, 256>>>(p_fc1, wl2, bn7, nullptr,
                                                     p_fc2, 256, 512, BATCH);
    }
    {
        int warps = BATCH * 40;
        fc_kernel<<<(warps * 32 + 255) / 256, 256>>>(p_fc2, wl3, nullptr, bl3,
                                                     out, 40, 256, BATCH);
    }
}

// round 15
// speedup vs baseline: 1.0086x; 1.0086x over previous
#include <cuda_runtime.h>
#include <cuda_bf16.h>
#include <cmath>

#define BATCH 16
#define NPTS  1024
#define KNN   20
#define EPSBN 1e-5f
#define SLOPE 0.2f

// ---------------- scratch (device globals; no allocations allowed) ----------------
__device__ float g_xT[BATCH * NPTS * 8];
__device__ float g_hcat[BATCH * NPTS * 512];
__device__ unsigned g_pd[(long long)BATCH * NPTS * NPTS];   // monotone keys
__device__ int   g_idx[BATCH * NPTS * KNN];
__device__ float g_YZ[BATCH * NPTS * 512];
__device__ float g_W[512 * 128];
__device__ float g_sq[BATCH * NPTS];
__device__ float g_pmax[8 * BATCH * 1024];
__device__ float g_psum[8 * BATCH * 1024];
__device__ float g_pool[BATCH * 2048];
__device__ float g_fc1[BATCH * 512];
__device__ float g_fc2[BATCH * 256];
// split-bf16 buffers
__device__ unsigned short g_Ahi[BATCH * NPTS * 512];
__device__ unsigned short g_Alo[BATCH * NPTS * 512];
__device__ unsigned short g_Bhi[1024 * 512];
__device__ unsigned short g_Blo[1024 * 512];
__device__ unsigned short g_Xhi[BATCH * NPTS * 32];
__device__ unsigned short g_Xlo[BATCH * NPTS * 32];

// ---------------- helpers ----------------
__device__ __forceinline__ unsigned long long pack2(float lo, float hi)
{
    unsigned long long r;
    asm("mov.b64 %0, {%1, %2};" : "=l"(r) : "f"(lo), "f"(hi));
    return r;
}
__device__ __forceinline__ void ffma2(unsigned long long& acc,
                                      unsigned long long a, unsigned long long b)
{
    asm("fma.rn.f32x2 %0, %1, %2, %0;" : "+l"(acc) : "l"(a), "l"(b));
}
__device__ __forceinline__ float2 unpack2(unsigned long long v)
{
    float lo, hi;
    asm("mov.b64 {%0, %1}, %2;" : "=f"(lo), "=f"(hi) : "l"(v));
    return make_float2(lo, hi);
}
__device__ __forceinline__ void mma_bf16(float* d, const unsigned* a, const unsigned* b)
{
    asm volatile(
        "mma.sync.aligned.m16n8k16.row.col.f32.bf16.bf16.f32 "
        "{%0,%1,%2,%3}, {%4,%5,%6,%7}, {%8,%9}, {%0,%1,%2,%3};"
        : "+f"(d[0]), "+f"(d[1]), "+f"(d[2]), "+f"(d[3])
        : "r"(a[0]), "r"(a[1]), "r"(a[2]), "r"(a[3]), "r"(b[0]), "r"(b[1]));
}
__device__ __forceinline__ unsigned short bf_bits(__nv_bfloat16 h)
{
    unsigned short s;
    memcpy(&s, &h, 2);
    return s;
}
__device__ __forceinline__ unsigned pk16(unsigned short a, unsigned short b)
{
    return (unsigned)a | ((unsigned)b << 16);
}
__device__ __forceinline__ unsigned fkey(float f)
{
    unsigned u = __float_as_uint(f);
    return (u & 0x80000000u) ? ~u : (u | 0x80000000u);
}

// ---------------- transpose x + split bf16 + sq, all fused ----------------
__global__ void transpose_x_split_kernel(const float* __restrict__ x,
                                         float* __restrict__ xT,
                                         unsigned short* __restrict__ Xhi,
                                         unsigned short* __restrict__ Xlo,
                                         float* __restrict__ sq)
{
    int p = blockIdx.x * blockDim.x + threadIdx.x;
    if (p >= BATCH * NPTS) return;
    int b = p / NPTS;
    int n = p % NPTS;
    const float* xb = x + (long long)b * 3 * NPTS + n;
    float v0 = xb[0], v1 = xb[NPTS], v2 = xb[2 * NPTS];
    *(float4*)&xT[p * 8]     = make_float4(v0, v1, v2, 0.f);
    *(float4*)&xT[p * 8 + 4] = make_float4(0.f, 0.f, 0.f, 0.f);
    sq[p] = v0 * v0 + v1 * v1 + v2 * v2;

    __nv_bfloat16 h0 = __float2bfloat16_rn(v0);
    __nv_bfloat16 h1 = __float2bfloat16_rn(v1);
    __nv_bfloat16 h2 = __float2bfloat16_rn(v2);
    __nv_bfloat16 l0 = __float2bfloat16_rn(v0 - __bfloat162float(h0));
    __nv_bfloat16 l1 = __float2bfloat16_rn(v1 - __bfloat162float(h1));
    __nv_bfloat16 l2 = __float2bfloat16_rn(v2 - __bfloat162float(h2));

    uint4 z = make_uint4(0, 0, 0, 0);
    uint4 vh = make_uint4(pk16(bf_bits(h0), bf_bits(h1)), pk16(bf_bits(h2), 0), 0, 0);
    uint4 vl = make_uint4(pk16(bf_bits(l0), bf_bits(l1)), pk16(bf_bits(l2), 0), 0, 0);
    uint4* ph = (uint4*)(Xhi + p * 32);
    uint4* pl = (uint4*)(Xlo + p * 32);
    ph[0] = vh; ph[1] = z; ph[2] = z; ph[3] = z;
    pl[0] = vl; pl[1] = z; pl[2] = z; pl[3] = z;
}

// ---------------- fp32 -> (hi, lo) bf16 split (w5) ----------------
__global__ void cvt_split4_kernel(const float* __restrict__ in,
                                  unsigned short* __restrict__ hi,
                                  unsigned short* __restrict__ lo, int n4)
{
    int i = blockIdx.x * blockDim.x + threadIdx.x;
    if (i >= n4) return;
    float4 v = ((const float4*)in)[i];
    __nv_bfloat16 h0 = __float2bfloat16_rn(v.x);
    __nv_bfloat16 h1 = __float2bfloat16_rn(v.y);
    __nv_bfloat16 h2 = __float2bfloat16_rn(v.z);
    __nv_bfloat16 h3 = __float2bfloat16_rn(v.w);
    __nv_bfloat16 l0 = __float2bfloat16_rn(v.x - __bfloat162float(h0));
    __nv_bfloat16 l1 = __float2bfloat16_rn(v.y - __bfloat162float(h1));
    __nv_bfloat16 l2 = __float2bfloat16_rn(v.z - __bfloat162float(h2));
    __nv_bfloat16 l3 = __float2bfloat16_rn(v.w - __bfloat162float(h3));
    uint2* hp = (uint2*)(hi + i * 4);
    uint2* lp = (uint2*)(lo + i * 4);
    *hp = make_uint2(pk16(bf_bits(h0), bf_bits(h1)), pk16(bf_bits(h2), bf_bits(h3)));
    *lp = make_uint2(pk16(bf_bits(l0), bf_bits(l1)), pk16(bf_bits(l2), bf_bits(l3)));
}

// ---------------- split-bf16 MMA Gram -> monotone keys --------------------------
__global__ void __launch_bounds__(256)
gram_mma_kernel(const unsigned short* __restrict__ Hhi,
                const unsigned short* __restrict__ Hlo,
                int ld, int K,
                const float* __restrict__ sq, unsigned* __restrict__ pd)
{
    __shared__ __align__(16) unsigned sah[128 * 20], sal[128 * 20],
                                      sbh[128 * 20], sbl[128 * 20];

    int b = blockIdx.z;
    long long hbase = (long long)b * NPTS * ld;
    const float* sqb = sq + b * NPTS;
    unsigned* pdb = pd + (long long)b * NPTS * NPTS;

    int tid = threadIdx.x;
    int lane = tid & 31;
    int w = tid >> 5;
    int wm = w & 1, wn = w >> 1;
    int gr = lane >> 2, tig = lane & 3;
    int bx = blockIdx.x, by = blockIdx.y;

    int l_row = tid >> 1;
    int q0 = (tid & 1) * 2;
    long long a_base = hbase + (long long)(by * 128 + l_row) * ld;
    long long b_base = hbase + (long long)(bx * 128 + l_row) * ld;

    int nk = K >> 5;

    uint4 pa_h[2], pa_l[2], pb_h[2], pb_l[2];
    #pragma unroll
    for (int q = 0; q < 2; ++q) {
        pa_h[q] = *(const uint4*)(Hhi + a_base + (q0 + q) * 8);
        pa_l[q] = *(const uint4*)(Hlo + a_base + (q0 + q) * 8);
        pb_h[q] = *(const uint4*)(Hhi + b_base + (q0 + q) * 8);
        pb_l[q] = *(const uint4*)(Hlo + b_base + (q0 + q) * 8);
    }

    float acc[4][4][4];
    #pragma unroll
    for (int mt = 0; mt < 4; ++mt)
        #pragma unroll
        for (int nt = 0; nt < 4; ++nt)
            #pragma unroll
            for (int c = 0; c < 4; ++c)
                acc[mt][nt][c] = 0.f;

    for (int kt = 0; kt < nk; ++kt) {
        #pragma unroll
        for (int q = 0; q < 2; ++q) {
            *(uint4*)&sah[l_row * 20 + (q0 + q) * 4] = pa_h[q];
            *(uint4*)&sal[l_row * 20 + (q0 + q) * 4] = pa_l[q];
            *(uint4*)&sbh[l_row * 20 + (q0 + q) * 4] = pb_h[q];
            *(uint4*)&sbl[l_row * 20 + (q0 + q) * 4] = pb_l[q];
        }
        __syncthreads();

        if (kt + 1 < nk) {
            long long koff = (long long)(kt + 1) * 32;
            #pragma unroll
            for (int q = 0; q < 2; ++q) {
                pa_h[q] = *(const uint4*)(Hhi + a_base + koff + (q0 + q) * 8);
                pa_l[q] = *(const uint4*)(Hlo + a_base + koff + (q0 + q) * 8);
                pb_h[q] = *(const uint4*)(Hhi + b_base + koff + (q0 + q) * 8);
                pb_l[q] = *(const uint4*)(Hlo + b_base + koff + (q0 + q) * 8);
            }
        }

        #pragma unroll
        for (int s = 0; s < 2; ++s) {
            unsigned ahf[4][4], alf[4][4];
            #pragma unroll
            for (int mt = 0; mt < 4; ++mt) {
                int r0 = wm * 64 + mt * 16 + gr;
                int p = s * 8 + tig;
                ahf[mt][0] = sah[r0 * 20 + p];
                ahf[mt][1] = sah[(r0 + 8) * 20 + p];
                ahf[mt][2] = sah[r0 * 20 + p + 4];
                ahf[mt][3] = sah[(r0 + 8) * 20 + p + 4];
                alf[mt][0] = sal[r0 * 20 + p];
                alf[mt][1] = sal[(r0 + 8) * 20 + p];
                alf[mt][2] = sal[r0 * 20 + p + 4];
                alf[mt][3] = sal[(r0 + 8) * 20 + p + 4];
            }
            unsigned bhf[4][2], blf[4][2];
            #pragma unroll
            for (int nt = 0; nt < 4; ++nt) {
                int n0 = wn * 32 + nt * 8 + gr;
                int p = s * 8 + tig;
                bhf[nt][0] = sbh[n0 * 20 + p];
                bhf[nt][1] = sbh[n0 * 20 + p + 4];
                blf[nt][0] = sbl[n0 * 20 + p];
                blf[nt][1] = sbl[n0 * 20 + p + 4];
            }
            #pragma unroll
            for (int mt = 0; mt < 4; ++mt)
                #pragma unroll
                for (int nt = 0; nt < 4; ++nt) {
                    mma_bf16(acc[mt][nt], ahf[mt], bhf[nt]);
                    mma_bf16(acc[mt][nt], ahf[mt], blf[nt]);
                    mma_bf16(acc[mt][nt], alf[mt], bhf[nt]);
                }
        }
        __syncthreads();
    }

    #pragma unroll
    for (int mt = 0; mt < 4; ++mt) {
        int r0 = by * 128 + wm * 64 + mt * 16 + gr;
        float sq0 = sqb[r0];
        float sq1 = sqb[r0 + 8];
        #pragma unroll
        for (int nt = 0; nt < 4; ++nt) {
            int c = bx * 128 + wn * 32 + nt * 8 + 2 * tig;
            float sc0 = sqb[c], sc1 = sqb[c + 1];
            *(uint2*)&pdb[(long long)r0 * NPTS + c] =
                make_uint2(fkey(2.f * acc[mt][nt][0] - sq0 - sc0),
                           fkey(2.f * acc[mt][nt][1] - sq0 - sc1));
            *(uint2*)&pdb[(long long)(r0 + 8) * NPTS + c] =
                make_uint2(fkey(2.f * acc[mt][nt][2] - sq1 - sc0),
                           fkey(2.f * acc[mt][nt][3] - sq1 - sc1));
        }
    }
}

// ---------------- 128x128 tiled SGEMM, f32x2 core (YZ GEMM) ----------------
__global__ void __launch_bounds__(256)
sgemm_nt_kernel(const float* __restrict__ A, const float* __restrict__ Bw,
                float* __restrict__ C,
                int M, int Nn, int K, int lda, int ldb, int ldc)
{
    __shared__ float As[8][128];
    __shared__ float Bs[8][128];

    int tid = threadIdx.x;
    int tx = tid & 15;
    int ty = tid >> 4;
    int bx = blockIdx.x, by = blockIdx.y;

    int l_row = tid >> 1;
    int l_k0  = (tid & 1) * 4;

    const float* aptr = A + (long long)(by * 128 + l_row) * lda + l_k0;
    const float* bptr = Bw + (long long)(bx * 128 + l_row) * ldb + l_k0;

    float4 ra = *(const float4*)aptr;
    float4 rb = *(const float4*)bptr;

    unsigned long long acc2[8][4];
    #pragma unroll
    for (int i = 0; i < 8; ++i)
        #pragma unroll
        for (int j = 0; j < 4; ++j)
            acc2[i][j] = 0ull;

    for (int kt = 0; kt < K; kt += 8) {
        As[l_k0 + 0][l_row] = ra.x;
        As[l_k0 + 1][l_row] = ra.y;
        As[l_k0 + 2][l_row] = ra.z;
        As[l_k0 + 3][l_row] = ra.w;
        Bs[l_k0 + 0][l_row] = rb.x;
        Bs[l_k0 + 1][l_row] = rb.y;
        Bs[l_k0 + 2][l_row] = rb.z;
        Bs[l_k0 + 3][l_row] = rb.w;
        __syncthreads();

        if (kt + 8 < K) {
            ra = *(const float4*)(aptr + kt + 8);
            rb = *(const float4*)(bptr + kt + 8);
        }

        #pragma unroll
        for (int kk = 0; kk < 8; ++kk) {
            float4 a0 = *(const float4*)&As[kk][ty * 8];
            float4 a1 = *(const float4*)&As[kk][ty * 8 + 4];
            float4 b0 = *(const float4*)&Bs[kk][tx * 8];
            float4 b1 = *(const float4*)&Bs[kk][tx * 8 + 4];

            unsigned long long bp[4];
            bp[0] = pack2(b0.x, b0.y);
            bp[1] = pack2(b0.z, b0.w);
            bp[2] = pack2(b1.x, b1.y);
            bp[3] = pack2(b1.z, b1.w);

            float a[8] = {a0.x, a0.y, a0.z, a0.w, a1.x, a1.y, a1.z, a1.w};
            #pragma unroll
            for (int i = 0; i < 8; ++i) {
                unsigned long long ap = pack2(a[i], a[i]);
                #pragma unroll
                for (int j = 0; j < 4; ++j)
                    ffma2(acc2[i][j], ap, bp[j]);
            }
        }
        __syncthreads();
    }

    #pragma unroll
    for (int i = 0; i < 8; ++i) {
        int gm = by * 128 + ty * 8 + i;
        #pragma unroll
        for (int jj = 0; jj < 2; ++jj) {
            float4 v4;
            float2 p0 = unpack2(acc2[i][jj * 2]);
            float2 p1 = unpack2(acc2[i][jj * 2 + 1]);
            v4.x = p0.x; v4.y = p0.y; v4.z = p1.x; v4.w = p1.y;
            *(float4*)&C[(long long)gm * ldc + bx * 128 + tx * 8 + jj * 4] = v4;
        }
    }
}

// ---------------- conv5 split-bf16 MMA + fused BN/LReLU + pooling ---------------
__global__ void __launch_bounds__(256)
conv5_mma_kernel(const unsigned short* __restrict__ Ahi, const unsigned short* __restrict__ Alo,
                 const unsigned short* __restrict__ Bhi, const unsigned short* __restrict__ Blo,
                 const float* __restrict__ bn,
                 float* __restrict__ pmax, float* __restrict__ psum)
{
    __shared__ __align__(16) union SM {
        struct { unsigned ah[128 * 20], al[128 * 20], bh[128 * 20], bl[128 * 20]; } t;
        struct { float rmax[2][128]; float rsum[2][128]; } r;
    } sm;

    int tid = threadIdx.x;
    int lane = tid & 31;
    int w = tid >> 5;
    int wm = w & 1, wn = w >> 1;
    int gr = lane >> 2, tig = lane & 3;
    int bx = blockIdx.x, by = blockIdx.y;

    int l_row = tid >> 1;
    int q0 = (tid & 1) * 2;
    long long a_base = (long long)(by * 128 + l_row) * 512;
    long long b_base = (long long)(bx * 128 + l_row) * 512;

    uint4 pa_h[2], pa_l[2], pb_h[2], pb_l[2];
    #pragma unroll
    for (int q = 0; q < 2; ++q) {
        pa_h[q] = *(const uint4*)(Ahi + a_base + (q0 + q) * 8);
        pa_l[q] = *(const uint4*)(Alo + a_base + (q0 + q) * 8);
        pb_h[q] = *(const uint4*)(Bhi + b_base + (q0 + q) * 8);
        pb_l[q] = *(const uint4*)(Blo + b_base + (q0 + q) * 8);
    }

    float acc[4][4][4];
    #pragma unroll
    for (int mt = 0; mt < 4; ++mt)
        #pragma unroll
        for (int nt = 0; nt < 4; ++nt)
            #pragma unroll
            for (int c = 0; c < 4; ++c)
                acc[mt][nt][c] = 0.f;

    for (int kt = 0; kt < 16; ++kt) {
        #pragma unroll
        for (int q = 0; q < 2; ++q) {
            *(uint4*)&sm.t.ah[l_row * 20 + (q0 + q) * 4] = pa_h[q];
            *(uint4*)&sm.t.al[l_row * 20 + (q0 + q) * 4] = pa_l[q];
            *(uint4*)&sm.t.bh[l_row * 20 + (q0 + q) * 4] = pb_h[q];
            *(uint4*)&sm.t.bl[l_row * 20 + (q0 + q) * 4] = pb_l[q];
        }
        __syncthreads();

        if (kt + 1 < 16) {
            long long koff = (long long)(kt + 1) * 32;
            #pragma unroll
            for (int q = 0; q < 2; ++q) {
                pa_h[q] = *(const uint4*)(Ahi + a_base + koff + (q0 + q) * 8);
                pa_l[q] = *(const uint4*)(Alo + a_base + koff + (q0 + q) * 8);
                pb_h[q] = *(const uint4*)(Bhi + b_base + koff + (q0 + q) * 8);
                pb_l[q] = *(const uint4*)(Blo + b_base + koff + (q0 + q) * 8);
            }
        }

        #pragma unroll
        for (int s = 0; s < 2; ++s) {
            unsigned ahf[4][4], alf[4][4];
            #pragma unroll
            for (int mt = 0; mt < 4; ++mt) {
                int r0 = wm * 64 + mt * 16 + gr;
                int p = s * 8 + tig;
                ahf[mt][0] = sm.t.ah[r0 * 20 + p];
                ahf[mt][1] = sm.t.ah[(r0 + 8) * 20 + p];
                ahf[mt][2] = sm.t.ah[r0 * 20 + p + 4];
                ahf[mt][3] = sm.t.ah[(r0 + 8) * 20 + p + 4];
                alf[mt][0] = sm.t.al[r0 * 20 + p];
                alf[mt][1] = sm.t.al[(r0 + 8) * 20 + p];
                alf[mt][2] = sm.t.al[r0 * 20 + p + 4];
                alf[mt][3] = sm.t.al[(r0 + 8) * 20 + p + 4];
            }
            unsigned bhf[4][2], blf[4][2];
            #pragma unroll
            for (int nt = 0; nt < 4; ++nt) {
                int n0 = wn * 32 + nt * 8 + gr;
                int p = s * 8 + tig;
                bhf[nt][0] = sm.t.bh[n0 * 20 + p];
                bhf[nt][1] = sm.t.bh[n0 * 20 + p + 4];
                blf[nt][0] = sm.t.bl[n0 * 20 + p];
                blf[nt][1] = sm.t.bl[n0 * 20 + p + 4];
            }
            #pragma unroll
            for (int mt = 0; mt < 4; ++mt)
                #pragma unroll
                for (int nt = 0; nt < 4; ++nt) {
                    mma_bf16(acc[mt][nt], ahf[mt], bhf[nt]);
                    mma_bf16(acc[mt][nt], ahf[mt], blf[nt]);
                    mma_bf16(acc[mt][nt], alf[mt], bhf[nt]);
                }
        }
        __syncthreads();
    }

    #pragma unroll
    for (int nt = 0; nt < 4; ++nt) {
        #pragma unroll
        for (int j = 0; j < 2; ++j) {
            int lcol = wn * 32 + nt * 8 + 2 * tig + j;
            int col = bx * 128 + lcol;
            float g  = bn[col];
            float be = bn[1024 + col];
            float mu = bn[2048 + col];
            float va = bn[3072 + col];
            float s = g * rsqrtf(va + EPSBN);
            float o = be - mu * s;
            float mx = -INFINITY, smv = 0.f;
            #pragma unroll
            for (int mt = 0; mt < 4; ++mt) {
                float v0 = s * acc[mt][nt][j] + o;
                v0 = v0 > 0.f ? v0 : SLOPE * v0;
                float v1 = s * acc[mt][nt][2 + j] + o;
                v1 = v1 > 0.f ? v1 : SLOPE * v1;
                mx = fmaxf(mx, fmaxf(v0, v1));
                smv += v0 + v1;
            }
            #pragma unroll
            for (int off = 4; off <= 16; off <<= 1) {
                mx = fmaxf(mx, __shfl_xor_sync(0xffffffffu, mx, off));
                smv += __shfl_xor_sync(0xffffffffu, smv, off);
            }
            if (gr == 0) {
                sm.r.rmax[wm][lcol] = mx;
                sm.r.rsum[wm][lcol] = smv;
            }
        }
    }
    __syncthreads();

    if (tid < 128) {
        int c = tid;
        float mx = fmaxf(sm.r.rmax[0][c], sm.r.rmax[1][c]);
        float s2 = sm.r.rsum[0][c] + sm.r.rsum[1][c];
        int b = by >> 3, chunk = by & 7;
        pmax[((long long)chunk * BATCH + b) * 1024 + bx * 128 + c] = mx;
        psum[((long long)chunk * BATCH + b) * 1024 + bx * 128 + c] = s2;
    }
}

// ---------------- final pool reduce over 8 chunks ----------------
__global__ void pool_reduce_kernel(const float* __restrict__ pmax,
                                   const float* __restrict__ psum,
                                   float* __restrict__ pool)
{
    int gi = blockIdx.x * blockDim.x + threadIdx.x;
    if (gi >= BATCH * 1024) return;
    int b = gi >> 10;
    int c = gi & 1023;
    float mx = -INFINITY, sm = 0.f;
    #pragma unroll
    for (int chunk = 0; chunk < 8; ++chunk) {
        mx = fmaxf(mx, pmax[((long long)chunk * BATCH + b) * 1024 + c]);
        sm += psum[((long long)chunk * BATCH + b) * 1024 + c];
    }
    pool[b * 2048 + c] = mx;
    pool[b * 2048 + 1024 + c] = sm * (1.f / (float)NPTS);
}

// ---------------- warp-per-row top-k: lane owns 32 CONTIGUOUS cols (LDG.128) ----
__global__ void __launch_bounds__(256) topk_warp_kernel(const unsigned* __restrict__ pd,
                                                        int* __restrict__ out)
{
    int warp_in_blk = threadIdx.x >> 5;
    int lane = threadIdx.x & 31;
    int row = blockIdx.x * 8 + warp_in_blk;

    // lane l owns columns [l*32, l*32+32): 8 x LDG.128
    const uint4* __restrict__ p =
        (const uint4*)(pd + (long long)row * NPTS + lane * 32);

    unsigned k[32];
    #pragma unroll
    for (int q = 0; q < 8; ++q) {
        uint4 v = p[q];
        k[q * 4 + 0] = v.x;
        k[q * 4 + 1] = v.y;
        k[q * 4 + 2] = v.z;
        k[q * 4 + 3] = v.w;
    }

    unsigned c0 = 0, c1 = 0, c2 = 0, c3 = 0;
    int i0 = 0, i1 = 0, i2 = 0, i3 = 0;
    #pragma unroll
    for (int j = 0; j < 32; ++j) {
        unsigned v = k[j];
        if (v > c3) {
            if (v > c2) {
                if (v > c1) {
                    if (v > c0) { c3=c2;i3=i2; c2=c1;i2=i1; c1=c0;i1=i0; c0=v;i0=j; }
                    else        { c3=c2;i3=i2; c2=c1;i2=i1; c1=v;i1=j; }
                } else          { c3=c2;i3=i2; c2=v;i2=j; }
            } else              { c3=v;i3=j; }
        }
    }

    int* __restrict__ o = out + (long long)row * KNN;

    #pragma unroll 1
    for (int it = 0; it < KNN; ++it) {
        unsigned m = __reduce_max_sync(0xffffffffu, c0);
        unsigned bal = __ballot_sync(0xffffffffu, c0 == m);
        int src = __ffs((int)bal) - 1;
        int gi = __shfl_sync(0xffffffffu, (lane << 5) | i0, src);  // col = lane*32+j
        if (lane == 0) o[it] = gi;

        if (lane == src) {
            k[i0] = 0u;
            c0 = c1; i0 = i1;
            c1 = c2; i1 = i2;
            c2 = c3; i2 = i3;
            c3 = 0;  i3 = 0;
            if (c0 == 0u) {
                #pragma unroll
                for (int j = 0; j < 32; ++j) {
                    unsigned v = k[j];
                    if (v > c3) {
                        if (v > c2) {
                            if (v > c1) {
                                if (v > c0) { c3=c2;i3=i2; c2=c1;i2=i1; c1=c0;i1=i0; c0=v;i0=j; }
                                else        { c3=c2;i3=i2; c2=c1;i2=i1; c1=v;i1=j; }
                            } else          { c3=c2;i3=i2; c2=v;i2=j; }
                        } else              { c3=v;i3=j; }
                    }
                }
            }
        }
    }
}

// ---------------- prepare edge weights: [wa ; wb - wa], K-padded ----------------
__global__ void prep_w_kernel(const float* __restrict__ w, float* __restrict__ Wc,
                              int O, int C, int Cpad)
{
    int i = blockIdx.x * blockDim.x + threadIdx.x;
    int tot = 2 * O * Cpad;
    if (i >= tot) return;
    int half = i / (O * Cpad);
    int j = i % (O * Cpad);
    int o = j / Cpad, c = j % Cpad;
    float v = 0.f;
    if (c < C)
        v = half == 0 ? w[o * 2 * C + c]
                      : w[o * 2 * C + C + c] - w[o * 2 * C + c];
    Wc[half * O * Cpad + o * Cpad + c] = v;
}

// ---------------- FUSED gather + max_k + BN + LReLU + bf16 split + sq -----------
__global__ void gather_fused_kernel(const float* __restrict__ YZ,
                                    const int* __restrict__ idx,
                                    const float* __restrict__ bn,
                                    float* __restrict__ hcat,
                                    unsigned short* __restrict__ Ahi,
                                    unsigned short* __restrict__ Alo,
                                    float* __restrict__ sq,
                                    int O, int catoff, int writeSq)
{
    int b = blockIdx.y;
    int n0 = blockIdx.x * 8;
    int o4 = threadIdx.x;
    int py = threadIdx.y;
    int n = n0 + py;

    __shared__ int sidx[8][KNN];
    __shared__ float ssq[8][64];
    int bw = blockDim.x * 8;
    for (int t = threadIdx.y * blockDim.x + threadIdx.x; t < 8 * KNN; t += bw)
        sidx[t / KNN][t % KNN] = idx[((long long)b * NPTS + n0 + t / KNN) * KNN + t % KNN];
    __syncthreads();

    int ld = 2 * O;
    const float* base = YZ + (long long)b * NPTS * ld;

    float4 zc = *(const float4*)&base[(long long)n * ld + O + o4 * 4];
    float4 mx = make_float4(-INFINITY, -INFINITY, -INFINITY, -INFINITY);
    float4 mn = make_float4(INFINITY, INFINITY, INFINITY, INFINITY);
    #pragma unroll
    for (int kk = 0; kk < KNN; ++kk) {
        float4 y = *(const float4*)&base[(long long)sidx[py][kk] * ld + o4 * 4];
        mx.x = fmaxf(mx.x, y.x); mn.x = fminf(mn.x, y.x);
        mx.y = fmaxf(mx.y, y.y); mn.y = fminf(mn.y, y.y);
        mx.z = fmaxf(mx.z, y.z); mn.z = fminf(mn.z, y.z);
        mx.w = fmaxf(mx.w, y.w); mn.w = fminf(mn.w, y.w);
    }

    float4 g4  = *(const float4*)&bn[o4 * 4];
    float4 be4 = *(const float4*)&bn[O + o4 * 4];
    float4 mu4 = *(const float4*)&bn[2 * O + o4 * 4];
    float4 va4 = *(const float4*)&bn[3 * O + o4 * 4];

    float4 r;
    {
        float s = g4.x * rsqrtf(va4.x + EPSBN);
        float z = (s >= 0.f ? mx.x : mn.x) + zc.x;
        float v = s * z + (be4.x - mu4.x * s);
        r.x = v > 0.f ? v : SLOPE * v;
    }
    {
        float s = g4.y * rsqrtf(va4.y + EPSBN);
        float z = (s >= 0.f ? mx.y : mn.y) + zc.y;
        float v = s * z + (be4.y - mu4.y * s);
        r.y = v > 0.f ? v : SLOPE * v;
    }
    {
        float s = g4.z * rsqrtf(va4.z + EPSBN);
        float z = (s >= 0.f ? mx.z : mn.z) + zc.z;
        float v = s * z + (be4.z - mu4.z * s);
        r.z = v > 0.f ? v : SLOPE * v;
    }
    {
        float s = g4.w * rsqrtf(va4.w + EPSBN);
        float z = (s >= 0.f ? mx.w : mn.w) + zc.w;
        float v = s * z + (be4.w - mu4.w * s);
        r.w = v > 0.f ? v : SLOPE * v;
    }

    long long off = ((long long)b * NPTS + n) * 512 + catoff + o4 * 4;
    *(float4*)&hcat[off] = r;

    __nv_bfloat16 h0 = __float2bfloat16_rn(r.x);
    __nv_bfloat16 h1 = __float2bfloat16_rn(r.y);
    __nv_bfloat16 h2 = __float2bfloat16_rn(r.z);
    __nv_bfloat16 h3 = __float2bfloat16_rn(r.w);
    __nv_bfloat16 l0 = __float2bfloat16_rn(r.x - __bfloat162float(h0));
    __nv_bfloat16 l1 = __float2bfloat16_rn(r.y - __bfloat162float(h1));
    __nv_bfloat16 l2 = __float2bfloat16_rn(r.z - __bfloat162float(h2));
    __nv_bfloat16 l3 = __float2bfloat16_rn(r.w - __bfloat162float(h3));
    *(uint2*)(Ahi + off) = make_uint2(pk16(bf_bits(h0), bf_bits(h1)),
                                      pk16(bf_bits(h2), bf_bits(h3)));
    *(uint2*)(Alo + off) = make_uint2(pk16(bf_bits(l0), bf_bits(l1)),
                                      pk16(bf_bits(l2), bf_bits(l3)));

    if (writeSq) {
        ssq[py][o4] = r.x * r.x + r.y * r.y + r.z * r.z + r.w * r.w;
        __syncthreads();
        if (o4 == 0) {
            float s = 0.f;
            for (int j = 0; j < blockDim.x; ++j) s += ssq[py][j];
            sq[(long long)b * NPTS + n] = s;
        }
    }
}

// ---------------- FC layer: warp per (b,o) ----------------
__global__ void fc_kernel(const float* __restrict__ in, const float* __restrict__ W,
                          const float* __restrict__ bn, const float* __restrict__ bias,
                          float* __restrict__ out, int O, int K, int Bn)
{
    int gw = (blockIdx.x * blockDim.x + threadIdx.x) >> 5;
    int lane = threadIdx.x & 31;
    if (gw >= Bn * O) return;
    int b = gw / O, o = gw % O;
    float acc = 0.f;
    const float* ip = in + (long long)b * K;
    const float* wp = W + (long long)o * K;
    for (int k = lane; k < K; k += 32) acc += ip[k] * wp[k];
    #pragma unroll
    for (int off = 16; off > 0; off >>= 1)
        acc += __shfl_down_sync(0xffffffffu, acc, off);
    if (lane == 0) {
        float v = acc;
        if (bn) {
            float g  = bn[o];
            float be = bn[O + o];
            float mu = bn[2 * O + o];
            float va = bn[3 * O + o];
            float s = g * rsqrtf(va + EPSBN);
            v = s * v + (be - mu * s);
            v = v > 0.f ? v : SLOPE * v;
        } else {
            v += bias[o];
        }
        out[(long long)b * O + o] = v;
    }
}

// ---------------- host orchestration (default + 1 side stream) ----------------
extern "C" void kernel_launch(void* const* d_in, const int* in_sizes, int n_in,
                              void* d_out, int out_size)
{
    (void)in_sizes; (void)n_in; (void)out_size;
    const float* x   = (const float*)d_in[0];
    const float* w1  = (const float*)d_in[1];
    const float* bn1 = (const float*)d_in[2];
    const float* w2  = (const float*)d_in[3];
    const float* bn2 = (const float*)d_in[4];
    const float* w3  = (const float*)d_in[5];
    const float* bn3 = (const float*)d_in[6];
    const float* w4  = (const float*)d_in[7];
    const float* bn4 = (const float*)d_in[8];
    const float* w5  = (const float*)d_in[9];
    const float* bn5 = (const float*)d_in[10];
    const float* wl1 = (const float*)d_in[11];
    const float* bn6 = (const float*)d_in[12];
    const float* wl2 = (const float*)d_in[13];
    const float* bn7 = (const float*)d_in[14];
    const float* wl3 = (const float*)d_in[15];
    const float* bl3 = (const float*)d_in[16];
    float* out = (float*)d_out;

    float *p_xT, *p_hcat, *p_YZ, *p_W, *p_sq, *p_pmax, *p_psum,
          *p_pool, *p_fc1, *p_fc2;
    unsigned* p_pd;
    int* p_idx;
    unsigned short *p_Ahi, *p_Alo, *p_Bhi, *p_Blo, *p_Xhi, *p_Xlo;
    cudaGetSymbolAddress((void**)&p_xT,   g_xT);
    cudaGetSymbolAddress((void**)&p_hcat, g_hcat);
    cudaGetSymbolAddress((void**)&p_pd,   g_pd);
    cudaGetSymbolAddress((void**)&p_idx,  g_idx);
    cudaGetSymbolAddress((void**)&p_YZ,   g_YZ);
    cudaGetSymbolAddress((void**)&p_W,    g_W);
    cudaGetSymbolAddress((void**)&p_sq,   g_sq);
    cudaGetSymbolAddress((void**)&p_pmax, g_pmax);
    cudaGetSymbolAddress((void**)&p_psum, g_psum);
    cudaGetSymbolAddress((void**)&p_pool, g_pool);
    cudaGetSymbolAddress((void**)&p_fc1,  g_fc1);
    cudaGetSymbolAddress((void**)&p_fc2,  g_fc2);
    cudaGetSymbolAddress((void**)&p_Ahi,  g_Ahi);
    cudaGetSymbolAddress((void**)&p_Alo,  g_Alo);
    cudaGetSymbolAddress((void**)&p_Bhi,  g_Bhi);
    cudaGetSymbolAddress((void**)&p_Blo,  g_Blo);
    cudaGetSymbolAddress((void**)&p_Xhi,  g_Xhi);
    cudaGetSymbolAddress((void**)&p_Xlo,  g_Xlo);

    static cudaStream_t s_side = nullptr;
    static cudaEvent_t evf[4], evj[4], evW0, evW;
    if (!s_side) {
        cudaStreamCreateWithFlags(&s_side, cudaStreamNonBlocking);
        for (int i = 0; i < 4; ++i) {
            cudaEventCreateWithFlags(&evf[i], cudaEventDisableTiming);
            cudaEventCreateWithFlags(&evj[i], cudaEventDisableTiming);
        }
        cudaEventCreateWithFlags(&evW0, cudaEventDisableTiming);
        cudaEventCreateWithFlags(&evW, cudaEventDisableTiming);
    }

    // side stream: convert w5 to split bf16
    cudaEventRecord(evW0, 0);
    cudaStreamWaitEvent(s_side, evW0, 0);
    cvt_split4_kernel<<<(1024 * 512 / 4 + 255) / 256, 256, 0, s_side>>>(
        w5, p_Bhi, p_Blo, 1024 * 512 / 4);
    cudaEventRecord(evW, s_side);

    // x -> xT fp32 + Xhi/Xlo bf16 + sq, all fused
    {
        int tot = BATCH * NPTS;
        transpose_x_split_kernel<<<(tot + 255) / 256, 256>>>(x, p_xT, p_Xhi, p_Xlo, p_sq);
    }

    struct Blk {
        const float* h; int lda, C, Cpad, O;
        const unsigned short *hhi, *hlo; int hld, Kmma;
        const float* w; const float* bn; int catoff;
    };
    Blk blks[4] = {
        { p_xT,         8,   3,   8,   64,  p_Xhi,       p_Xlo,       32,  32,  w1, bn1, 0   },
        { p_hcat + 0,   512, 64,  64,  64,  p_Ahi,       p_Alo,       512, 64,  w2, bn2, 64  },
        { p_hcat + 64,  512, 64,  64,  128, p_Ahi + 64,  p_Alo + 64,  512, 64,  w3, bn3, 128 },
        { p_hcat + 128, 512, 128, 128, 256, p_Ahi + 128, p_Alo + 128, 512, 128, w4, bn4, 256 },
    };

    for (int i = 0; i < 4; ++i) {
        const Blk& B = blks[i];

        // fork: side stream does prep_w + YZ GEMM
        cudaEventRecord(evf[i], 0);
        cudaStreamWaitEvent(s_side, evf[i], 0);
        {
            int tot = 2 * B.O * B.Cpad;
            prep_w_kernel<<<(tot + 255) / 256, 256, 0, s_side>>>(B.w, p_W, B.O, B.C, B.Cpad);
            dim3 grid((2 * B.O) / 128, (BATCH * NPTS) / 128, 1);
            sgemm_nt_kernel<<<grid, 256, 0, s_side>>>(B.h, p_W, p_YZ,
                BATCH * NPTS, 2 * B.O, B.Cpad, B.lda, B.Cpad, 2 * B.O);
            cudaEventRecord(evj[i], s_side);
        }

        // main: pd keys via split-bf16 MMA Gram, then topk
        {
            dim3 grid(8, 8, BATCH);
            gram_mma_kernel<<<grid, 256>>>(B.hhi, B.hlo, B.hld, B.Kmma, p_sq, p_pd);
        }
        topk_warp_kernel<<<(BATCH * NPTS) / 8, 256>>>(p_pd, p_idx);

        // join, then fused gather
        cudaStreamWaitEvent(0, evj[i], 0);
        {
            dim3 blk(B.O / 4, 8);
            gather_fused_kernel<<<dim3(NPTS / 8, BATCH), blk>>>(
                p_YZ, p_idx, B.bn, p_hcat, p_Ahi, p_Alo, p_sq,
                B.O, B.catoff, i < 3 ? 1 : 0);
        }
    }

    // conv5 tensor-core GEMM + fused pooling
    cudaStreamWaitEvent(0, evW, 0);
    {
        dim3 grid(8, 128);
        conv5_mma_kernel<<<grid, 256>>>(p_Ahi, p_Alo, p_Bhi, p_Blo, bn5, p_pmax, p_psum);
    }
    {
        int tot = BATCH * 1024;
        pool_reduce_kernel<<<(tot + 255) / 256, 256>>>(p_pmax, p_psum, p_pool);
    }

    {
        int warps = BATCH * 512;
        fc_kernel<<<(warps * 32 + 255) / 256, 256>>>(p_pool, wl1, bn6, nullptr,
                                                     p_fc1, 512, 2048, BATCH);
    }
    {
        int warps = BATCH * 256;
        fc_kernel<<<(warps * 32 + 255) / 256, 256>>>(p_fc1, wl2, bn7, nullptr,
                                                     p_fc2, 256, 512, BATCH);
    }
    {
        int warps = BATCH * 40;
        fc_kernel<<<(warps * 32 + 255) / 256, 256>>>(p_fc2, wl3, nullptr, bl3,
                                                     out, 40, 256, BATCH);
    }
}